// round 7
// baseline (speedup 1.0000x reference)
#include <cuda_runtime.h>
#include <cuda_fp16.h>
#include <cstdint>
#include <math.h>

#define E_ 8
#define H_ 2048
#define F_ 1024
#define D_ 2048
#define T_ 2048
#define TOPK_ 4
#define R_ 8
#define SCALING_ 2.0f
#define LIMIT_ 7.0f
#define ACT_ALPHA_ 1.702f

// ---- scratch (__device__ globals; allocation-free per harness rules) ----
__device__ float g_w[E_ * T_];                 // routing weight per (e,t)
__device__ int   g_cnt[E_];                    // active tokens per expert
__device__ int   g_list[E_ * T_];              // [e][slot] -> token
__device__ int   g_slot[E_ * T_];              // [e][t] -> slot or -1
__device__ float g_xa[E_ * T_ * R_];           // compacted [e][slot][r]
__device__ float g_la2[E_ * T_ * R_];          // compacted [e][slot][r]
__device__ __half g_xhi[(size_t)T_ * H_];
__device__ __half g_xlo[(size_t)T_ * H_];
__device__ __half g_w1h[(size_t)E_ * D_ * H_];   // gate_up^T [e][d][h], fp16
__device__ __half g_w2h[(size_t)E_ * H_ * F_];   // down^T [e][h][f], fp16
__device__ __half g_gwhi[(size_t)E_ * T_ * F_];  // compacted gatedw hi
__device__ __half g_gwlo[(size_t)E_ * T_ * F_];  // compacted gatedw lo
__device__ float g_outc[(size_t)E_ * T_ * H_];   // per-expert contributions

// ---- helpers ----
__device__ __forceinline__ void split2h(float v, __half& h, __half& l) {
    h = __float2half_rn(v);
    l = __float2half_rn(v - __half2float(h));
}

#define CP16(dst_u32, src_ptr) \
    asm volatile("cp.async.cg.shared.global [%0], [%1], 16;" :: "r"(dst_u32), "l"(src_ptr))
#define CP_COMMIT asm volatile("cp.async.commit_group;")
#define CP_WAIT1  asm volatile("cp.async.wait_group 1;")

__device__ __forceinline__ void ldsm4(uint32_t& r0, uint32_t& r1, uint32_t& r2,
                                      uint32_t& r3, uint32_t addr) {
    asm volatile("ldmatrix.sync.aligned.m8n8.x4.shared.b16 {%0,%1,%2,%3}, [%4];"
        : "=r"(r0), "=r"(r1), "=r"(r2), "=r"(r3) : "r"(addr));
}

__device__ __forceinline__ void mma16816(float* acc, uint32_t a0, uint32_t a1,
                                         uint32_t a2, uint32_t a3,
                                         uint32_t b0, uint32_t b1) {
    asm volatile(
        "mma.sync.aligned.m16n8k16.row.col.f32.f16.f16.f32 "
        "{%0,%1,%2,%3}, {%4,%5,%6,%7}, {%8,%9}, {%0,%1,%2,%3};"
        : "+f"(acc[0]), "+f"(acc[1]), "+f"(acc[2]), "+f"(acc[3])
        : "r"(a0), "r"(a1), "r"(a2), "r"(a3), "r"(b0), "r"(b1));
}

// smem stage layout (bytes): Ahi 0, Alo 12288, B 24576; stage stride 36864
// rows: 32 fp16 data (64 B) + 32 B pad = 96 B.  3 stages (single-sync ring).
#define STG_ 36864
#define NSTG_ 3
#define SMEM_SZ_ (NSTG_ * STG_)

// 2-term split mma over one k32 chunk (2 k16 steps), warp tile 64x64.
// a_base/b_base: lane-dependent ldmatrix byte offsets within their arrays.
__device__ __forceinline__ void compute_chunk(uint32_t st, float acc[4][8][4],
                                              int a_base, int b_base) {
    uint32_t Ahi = st, Alo = st + 12288, Bs = st + 24576;
#pragma unroll
    for (int ks = 0; ks < 2; ks++) {
        int kb = ks * 32;
        uint32_t B[8][2];
#pragma unroll
        for (int p = 0; p < 4; p++) {   // each x4 covers ni = 2p, 2p+1
            uint32_t r0, r1, r2, r3;
            ldsm4(r0, r1, r2, r3, Bs + b_base + p * 1536 + kb);
            B[2 * p][0] = r0; B[2 * p][1] = r1;
            B[2 * p + 1][0] = r2; B[2 * p + 1][1] = r3;
        }
        uint32_t A[4][4];
#pragma unroll
        for (int mi = 0; mi < 4; mi++)
            ldsm4(A[mi][0], A[mi][1], A[mi][2], A[mi][3],
                  Ahi + a_base + mi * 1536 + kb);
#pragma unroll
        for (int ni = 0; ni < 8; ni++)       // ah * b
#pragma unroll
            for (int mi = 0; mi < 4; mi++)
                mma16816(acc[mi][ni], A[mi][0], A[mi][1], A[mi][2], A[mi][3],
                         B[ni][0], B[ni][1]);
#pragma unroll
        for (int mi = 0; mi < 4; mi++)
            ldsm4(A[mi][0], A[mi][1], A[mi][2], A[mi][3],
                  Alo + a_base + mi * 1536 + kb);
#pragma unroll
        for (int ni = 0; ni < 8; ni++)       // al * b
#pragma unroll
            for (int mi = 0; mi < 4; mi++)
                mma16816(acc[mi][ni], A[mi][0], A[mi][1], A[mi][2], A[mi][3],
                         B[ni][0], B[ni][1]);
    }
}

// ===========================================================================
// zero counters (graph replays need re-init every launch)
// ===========================================================================
__global__ void k_zero() {
    if (threadIdx.x < E_) g_cnt[threadIdx.x] = 0;
}

// ===========================================================================
// K0: routing weights + per-expert compacted token lists
// ===========================================================================
__global__ void k_route(const float* __restrict__ rw, const int* __restrict__ idx) {
    int t = blockIdx.x * blockDim.x + threadIdx.x;
    if (t >= T_) return;
    float acc[E_];
    int act[E_];
#pragma unroll
    for (int j = 0; j < E_; j++) { acc[j] = 0.0f; act[j] = 0; }
    for (int k = 0; k < TOPK_; k++) {
        int e = idx[t * TOPK_ + k];
        float v = rw[t * TOPK_ + k];
#pragma unroll
        for (int j = 0; j < E_; j++)
            if (j == e) { acc[j] += v; act[j] = 1; }
    }
#pragma unroll
    for (int j = 0; j < E_; j++) {
        g_w[j * T_ + t] = acc[j];
        int s = -1;
        if (act[j]) {
            s = atomicAdd(&g_cnt[j], 1);
            g_list[j * T_ + s] = t;
        }
        g_slot[j * T_ + t] = s;
    }
}

// ===========================================================================
// split X -> hi/lo fp16
// ===========================================================================
__global__ void k_split_x(const float* __restrict__ X) {
    int i = blockIdx.x * blockDim.x + threadIdx.x;  // one float4
    float4 v = ((const float4*)X)[i];
    __half h0, l0, h1, l1, h2, l2, h3, l3;
    split2h(v.x, h0, l0); split2h(v.y, h1, l1);
    split2h(v.z, h2, l2); split2h(v.w, h3, l3);
    __half2* ph = (__half2*)g_xhi;
    __half2* pl = (__half2*)g_xlo;
    ph[i * 2]     = __halves2half2(h0, h1);
    ph[i * 2 + 1] = __halves2half2(h2, h3);
    pl[i * 2]     = __halves2half2(l0, l1);
    pl[i * 2 + 1] = __halves2half2(l2, l3);
}

// ===========================================================================
// convert + transpose weights: src [E][RR][CC] fp32 -> dst [E][CC][RR] fp16
// ===========================================================================
__global__ void k_splitT(const float* __restrict__ src, __half* __restrict__ dst,
                         int RR, int CC) {
    __shared__ __half hs[32][36];
    int e = blockIdx.z;
    int c0 = blockIdx.x * 32, r0 = blockIdx.y * 32;
    int tx = threadIdx.x & 31, ty = threadIdx.x >> 5;
    const float* s = src + (size_t)e * RR * CC;
#pragma unroll
    for (int j = 0; j < 4; j++)
        hs[ty + 8 * j][tx] = __float2half_rn(s[(size_t)(r0 + ty + 8 * j) * CC + c0 + tx]);
    __syncthreads();
    size_t dbase = (size_t)e * RR * CC;
#pragma unroll
    for (int j = 0; j < 4; j++) {
        int cc = c0 + ty + 8 * j;
        dst[dbase + (size_t)cc * RR + r0 + tx] = hs[tx][ty + 8 * j];
    }
}

// ===========================================================================
// K1 (gathered): g_xa[e,slot,r] = x[tok,:] @ A1[e,:,r]
// ===========================================================================
__global__ void k_loraA1(const float* __restrict__ X, const float* __restrict__ A1) {
    int warp = (blockIdx.x * blockDim.x + threadIdx.x) >> 5;
    int lane = threadIdx.x & 31;
    int e = warp / T_, slot = warp % T_;
    if (slot >= g_cnt[e]) return;
    int t = g_list[e * T_ + slot];
    const float* xrow = X + (size_t)t * H_;
    float acc[R_];
#pragma unroll
    for (int r = 0; r < R_; r++) acc[r] = 0.0f;
    for (int h0 = lane * 4; h0 < H_; h0 += 128) {
        float4 xv = *(const float4*)(xrow + h0);
        const float* a = A1 + ((size_t)e * H_ + h0) * R_;
        float xs[4] = {xv.x, xv.y, xv.z, xv.w};
#pragma unroll
        for (int qd = 0; qd < 4; qd++) {
            float4 a0 = *(const float4*)(a + qd * R_);
            float4 a1 = *(const float4*)(a + qd * R_ + 4);
            acc[0] += xs[qd] * a0.x; acc[1] += xs[qd] * a0.y;
            acc[2] += xs[qd] * a0.z; acc[3] += xs[qd] * a0.w;
            acc[4] += xs[qd] * a1.x; acc[5] += xs[qd] * a1.y;
            acc[6] += xs[qd] * a1.z; acc[7] += xs[qd] * a1.w;
        }
    }
    float keep = 0.0f;
#pragma unroll
    for (int r = 0; r < R_; r++) {
        float v = acc[r];
#pragma unroll
        for (int off = 16; off; off >>= 1) v += __shfl_xor_sync(0xffffffff, v, off);
        if (lane == r) keep = v;
    }
    if (lane < R_) g_xa[(size_t)(e * T_ + slot) * R_ + lane] = keep;
}

// ===========================================================================
// K3 (gathered): g_la2[e,slot,r] = gatedw[e,slot,:] @ A2[e,:,r]
// ===========================================================================
__global__ void k_loraA2(const float* __restrict__ A2) {
    int warp = (blockIdx.x * blockDim.x + threadIdx.x) >> 5;
    int lane = threadIdx.x & 31;
    int e = warp / T_, slot = warp % T_;
    if (slot >= g_cnt[e]) return;
    const __half* ph = g_gwhi + (size_t)(e * T_ + slot) * F_;
    const __half* pl = g_gwlo + (size_t)(e * T_ + slot) * F_;
    float acc[R_];
#pragma unroll
    for (int r = 0; r < R_; r++) acc[r] = 0.0f;
    for (int f0 = lane * 4; f0 < F_; f0 += 128) {
        __half2 h0 = *(const __half2*)(ph + f0);
        __half2 h1 = *(const __half2*)(ph + f0 + 2);
        __half2 l0 = *(const __half2*)(pl + f0);
        __half2 l1 = *(const __half2*)(pl + f0 + 2);
        float xs[4] = {
            __half2float(h0.x) + __half2float(l0.x),
            __half2float(h0.y) + __half2float(l0.y),
            __half2float(h1.x) + __half2float(l1.x),
            __half2float(h1.y) + __half2float(l1.y)};
        const float* a = A2 + ((size_t)e * F_ + f0) * R_;
#pragma unroll
        for (int qd = 0; qd < 4; qd++) {
            float4 a0 = *(const float4*)(a + qd * R_);
            float4 a1 = *(const float4*)(a + qd * R_ + 4);
            acc[0] += xs[qd] * a0.x; acc[1] += xs[qd] * a0.y;
            acc[2] += xs[qd] * a0.z; acc[3] += xs[qd] * a0.w;
            acc[4] += xs[qd] * a1.x; acc[5] += xs[qd] * a1.y;
            acc[6] += xs[qd] * a1.z; acc[7] += xs[qd] * a1.w;
        }
    }
    float keep = 0.0f;
#pragma unroll
    for (int r = 0; r < R_; r++) {
        float v = acc[r];
#pragma unroll
        for (int off = 16; off; off >>= 1) v += __shfl_xor_sync(0xffffffff, v, off);
        if (lane == r) keep = v;
    }
    if (lane < R_) g_la2[(size_t)(e * T_ + slot) * R_ + lane] = keep;
}

// ===========================================================================
// K2 (gathered): HMMA GEMM1 over active tokens of expert e
// grid (D/128, 16 max m-tiles, E), 128 threads
// ===========================================================================
__global__ void __launch_bounds__(128, 2)
k_gemm1(const float* __restrict__ bias, const float* __restrict__ B1) {
    int e = blockIdx.z, m0 = blockIdx.y * 128, n0 = blockIdx.x * 128;
    int cnt = g_cnt[e];
    if (m0 >= cnt) return;
    extern __shared__ char smem[];
    uint32_t sb = (uint32_t)__cvta_generic_to_shared(smem);
    int tid = threadIdx.x;
    int wid = tid >> 5, lane = tid & 31;
    int wr = wid >> 1, wc = wid & 1, g = lane >> 2, q = lane & 3;

    // lane-dependent ldmatrix offsets
    int a_base = (wr * 64 + (lane & 15)) * 96 + (lane >> 4) * 16;
    int grp = lane >> 3, wth = lane & 7;
    int b_base = (wc * 64 + wth + ((grp >= 2) ? 8 : 0)) * 96 + (grp & 1) * 16;

    int tok = g_list[e * T_ + (m0 + tid < cnt ? m0 + tid : m0)];

    float acc[4][8][4];
#pragma unroll
    for (int a = 0; a < 4; a++)
#pragma unroll
        for (int b = 0; b < 8; b++)
#pragma unroll
            for (int c = 0; c < 4; c++) acc[a][b][c] = 0.0f;

    auto issue = [&](int c, int stage) {
        int k0 = c * 32;
        uint32_t a_hi = sb + stage * STG_ + tid * 96;
        const __half* sxh = g_xhi + (size_t)tok * H_ + k0;
        const __half* sxl = g_xlo + (size_t)tok * H_ + k0;
        const __half* swh = g_w1h + ((size_t)e * D_ + n0 + tid) * H_ + k0;
#pragma unroll
        for (int j = 0; j < 4; j++) {
            CP16(a_hi + j * 16,         sxh + j * 8);
            CP16(a_hi + 12288 + j * 16, sxl + j * 8);
            CP16(a_hi + 24576 + j * 16, swh + j * 8);
        }
    };
    issue(0, 0); CP_COMMIT;
    issue(1, 1); CP_COMMIT;
    const int NCH = H_ / 32;
    for (int c = 0; c < NCH; c++) {
        CP_WAIT1;
        __syncthreads();
        if (c + 2 < NCH) issue(c + 2, (c + 2) % NSTG_);
        CP_COMMIT;
        compute_chunk(sb + (c % NSTG_) * STG_, acc, a_base, b_base);
    }
    __syncthreads();   // protect smem reuse in epilogue

    // ---- epilogue ----
    float* xa_s   = (float*)smem;            // [128][8]
    float* b1_s   = (float*)(smem + 4096);   // [8][128]
    float* bias_s = (float*)(smem + 8192);   // [128]
    float* w_s    = (float*)(smem + 8704);   // [128]
    for (int i = tid; i < 1024; i += 128) {
        xa_s[i] = g_xa[((size_t)e * T_ + m0 + (i >> 3)) * 8 + (i & 7)] * SCALING_;
        b1_s[i] = B1[((size_t)e * 8 + (i >> 7)) * D_ + n0 + (i & 127)];
    }
    bias_s[tid] = bias[(size_t)e * D_ + n0 + tid];
    w_s[tid] = (m0 + tid < cnt) ? g_w[e * T_ + tok] : 0.0f;
    __syncthreads();

#pragma unroll
    for (int mi = 0; mi < 4; mi++) {
#pragma unroll
        for (int ni = 0; ni < 8; ni++) {
            int c = wc * 64 + ni * 8 + q * 2;
            float2 bia = *(const float2*)&bias_s[c];
#pragma unroll
            for (int h = 0; h < 2; h++) {
                int row = wr * 64 + mi * 16 + g + h * 8;
                if (m0 + row >= cnt) continue;
                float gate = acc[mi][ni][h * 2 + 0] + bia.x;
                float up   = acc[mi][ni][h * 2 + 1] + bia.y;
                const float* xr = &xa_s[row * 8];
#pragma unroll
                for (int p = 0; p < 8; p++) {
                    float2 b1v = *(const float2*)&b1_s[p * 128 + c];
                    gate += xr[p] * b1v.x;
                    up   += xr[p] * b1v.y;
                }
                gate = fminf(gate, LIMIT_);
                up = fminf(fmaxf(up, -LIMIT_), LIMIT_);
                float glu = gate / (1.0f + expf(-ACT_ALPHA_ * gate));
                float val = w_s[row] * (up + 1.0f) * glu;
                __half hh, ll; split2h(val, hh, ll);
                size_t oidx = ((size_t)e * T_ + m0 + row) * F_ + ((n0 + c) >> 1);
                g_gwhi[oidx] = hh; g_gwlo[oidx] = ll;
            }
        }
    }
}

// ===========================================================================
// K4 (gathered): per-expert HMMA GEMM2 -> g_outc[e][slot][h]
// grid (H/128, 16 max m-tiles, E), 128 threads
// ===========================================================================
__global__ void __launch_bounds__(128, 2)
k_gemm2(const float* __restrict__ bias2, const float* __restrict__ B2) {
    int e = blockIdx.z, m0 = blockIdx.y * 128, n0 = blockIdx.x * 128;
    int cnt = g_cnt[e];
    if (m0 >= cnt) return;
    extern __shared__ char smem[];
    uint32_t sb = (uint32_t)__cvta_generic_to_shared(smem);
    int tid = threadIdx.x;
    int wid = tid >> 5, lane = tid & 31;
    int wr = wid >> 1, wc = wid & 1, g = lane >> 2, q = lane & 3;

    int a_base = (wr * 64 + (lane & 15)) * 96 + (lane >> 4) * 16;
    int grp = lane >> 3, wth = lane & 7;
    int b_base = (wc * 64 + wth + ((grp >= 2) ? 8 : 0)) * 96 + (grp & 1) * 16;

    float acc[4][8][4];
#pragma unroll
    for (int a = 0; a < 4; a++)
#pragma unroll
        for (int b = 0; b < 8; b++)
#pragma unroll
            for (int c = 0; c < 4; c++) acc[a][b][c] = 0.0f;

    auto issue = [&](int c, int stage) {
        int f0 = c * 32;
        uint32_t a_hi = sb + stage * STG_ + tid * 96;
        const __half* sah = g_gwhi + ((size_t)e * T_ + m0 + tid) * F_ + f0;
        const __half* sal = g_gwlo + ((size_t)e * T_ + m0 + tid) * F_ + f0;
        const __half* sbh = g_w2h + ((size_t)e * H_ + n0 + tid) * F_ + f0;
#pragma unroll
        for (int j = 0; j < 4; j++) {
            CP16(a_hi + j * 16,         sah + j * 8);
            CP16(a_hi + 12288 + j * 16, sal + j * 8);
            CP16(a_hi + 24576 + j * 16, sbh + j * 8);
        }
    };
    issue(0, 0); CP_COMMIT;
    issue(1, 1); CP_COMMIT;
    const int NCH = F_ / 32;
    for (int c = 0; c < NCH; c++) {
        CP_WAIT1;
        __syncthreads();
        if (c + 2 < NCH) issue(c + 2, (c + 2) % NSTG_);
        CP_COMMIT;
        compute_chunk(sb + (c % NSTG_) * STG_, acc, a_base, b_base);
    }
    __syncthreads();   // protect smem reuse in epilogue

    // ---- epilogue: += SCALING*la2@B2 + w*bias2; store to outc ----
    float* la_s = (float*)smem;            // [128][8]
    float* b2_s = (float*)(smem + 4096);   // [8][128]
    float* bb_s = (float*)(smem + 8192);   // [128]
    float* w_s  = (float*)(smem + 8704);   // [128]
    for (int i = tid; i < 1024; i += 128) {
        la_s[i] = g_la2[((size_t)e * T_ + m0 + (i >> 3)) * 8 + (i & 7)] * SCALING_;
        b2_s[i] = B2[((size_t)e * 8 + (i >> 7)) * H_ + n0 + (i & 127)];
    }
    bb_s[tid] = bias2[(size_t)e * H_ + n0 + tid];
    {
        int gs = m0 + tid;
        w_s[tid] = (gs < cnt) ? g_w[e * T_ + g_list[e * T_ + gs]] : 0.0f;
    }
    __syncthreads();

#pragma unroll
    for (int mi = 0; mi < 4; mi++) {
#pragma unroll
        for (int ni = 0; ni < 8; ni++) {
            int c = wc * 64 + ni * 8 + q * 2;
            float2 bb = *(const float2*)&bb_s[c];
#pragma unroll
            for (int h = 0; h < 2; h++) {
                int row = wr * 64 + mi * 16 + g + h * 8;
                if (m0 + row >= cnt) continue;
                float v0 = acc[mi][ni][h * 2 + 0];
                float v1 = acc[mi][ni][h * 2 + 1];
                const float* la = &la_s[row * 8];
#pragma unroll
                for (int p = 0; p < 8; p++) {
                    float2 bv = *(const float2*)&b2_s[p * 128 + c];
                    v0 += la[p] * bv.x;
                    v1 += la[p] * bv.y;
                }
                float wt = w_s[row];
                v0 += wt * bb.x;
                v1 += wt * bb.y;
                *(float2*)(g_outc + ((size_t)e * T_ + m0 + row) * H_ + n0 + c) =
                    make_float2(v0, v1);
            }
        }
    }
}

// ===========================================================================
// K5: combine per-expert contributions -> out
// ===========================================================================
__global__ void __launch_bounds__(128)
k_combine(float* __restrict__ out) {
    int t = blockIdx.x;
    int tid = threadIdx.x;
    int slots[E_];
#pragma unroll
    for (int e = 0; e < E_; e++) slots[e] = g_slot[e * T_ + t];
#pragma unroll
    for (int k = 0; k < 4; k++) {
        int h = tid * 4 + k * 512;
        float4 acc = make_float4(0.f, 0.f, 0.f, 0.f);
#pragma unroll
        for (int e = 0; e < E_; e++) {
            int s = slots[e];
            if (s >= 0) {
                float4 v = *(const float4*)(g_outc + ((size_t)e * T_ + s) * H_ + h);
                acc.x += v.x; acc.y += v.y; acc.z += v.z; acc.w += v.w;
            }
        }
        *(float4*)(out + (size_t)t * H_ + h) = acc;
    }
}

// ===========================================================================
extern "C" void kernel_launch(void* const* d_in, const int* in_sizes, int n_in,
                              void* d_out, int out_size) {
    const float* x      = (const float*)d_in[0];
    const float* rw     = (const float*)d_in[1];
    const float* gup    = (const float*)d_in[2];
    const float* gup_b  = (const float*)d_in[3];
    const float* dn     = (const float*)d_in[4];
    const float* dn_b   = (const float*)d_in[5];
    const float* A1     = (const float*)d_in[6];
    const float* B1     = (const float*)d_in[7];
    const float* A2     = (const float*)d_in[8];
    const float* B2     = (const float*)d_in[9];
    const int*   ri     = (const int*)d_in[10];   // int32 (JAX x64 off)
    float* out = (float*)d_out;

    static bool attr_done = false;
    if (!attr_done) {
        cudaFuncSetAttribute(k_gemm1, cudaFuncAttributeMaxDynamicSharedMemorySize, SMEM_SZ_);
        cudaFuncSetAttribute(k_gemm2, cudaFuncAttributeMaxDynamicSharedMemorySize, SMEM_SZ_);
        attr_done = true;
    }

    __half *w1h, *w2h;
    cudaGetSymbolAddress((void**)&w1h, g_w1h);
    cudaGetSymbolAddress((void**)&w2h, g_w2h);

    k_zero<<<1, 32>>>();
    k_route<<<(T_ + 127) / 128, 128>>>(rw, ri);
    k_split_x<<<(T_ * H_ / 4) / 256, 256>>>(x);
    k_splitT<<<dim3(D_ / 32, H_ / 32, E_), 256>>>(gup, w1h, H_, D_);
    k_splitT<<<dim3(H_ / 32, F_ / 32, E_), 256>>>(dn, w2h, F_, H_);
    k_loraA1<<<(E_ * T_) / 8, 256>>>(x, A1);
    k_gemm1<<<dim3(D_ / 128, T_ / 128, E_), 128, SMEM_SZ_>>>(gup_b, B1);
    k_loraA2<<<(E_ * T_) / 8, 256>>>(A2);
    k_gemm2<<<dim3(H_ / 128, T_ / 128, E_), 128, SMEM_SZ_>>>(dn_b, B2);
    k_combine<<<T_, 128>>>(out);
}

// round 8
// speedup vs baseline: 1.1241x; 1.1241x over previous
#include <cuda_runtime.h>
#include <cuda_fp16.h>
#include <cstdint>
#include <math.h>

#define E_ 8
#define H_ 2048
#define F_ 1024
#define D_ 2048
#define T_ 2048
#define TOPK_ 4
#define R_ 8
#define SCALING_ 2.0f
#define LIMIT_ 7.0f
#define ACT_ALPHA_ 1.702f

// ---- scratch (__device__ globals; allocation-free per harness rules) ----
__device__ float g_w[E_ * T_];                 // routing weight per (e,t)
__device__ int   g_cnt[E_];                    // active tokens per expert
__device__ int   g_list[E_ * T_];              // [e][slot] -> token
__device__ int   g_slot[E_ * T_];              // [e][t] -> slot or -1
__device__ float g_xa[E_ * T_ * R_];           // compacted [e][slot][r]
__device__ float g_la2[E_ * T_ * R_];          // compacted [e][slot][r]
__device__ __half g_xhi[(size_t)T_ * H_];
__device__ __half g_xlo[(size_t)T_ * H_];
__device__ __half g_w1h[(size_t)E_ * D_ * H_];   // gate_up^T [e][d][h], fp16
__device__ __half g_w2h[(size_t)E_ * H_ * F_];   // down^T [e][h][f], fp16
__device__ __half g_gw[(size_t)E_ * T_ * F_];    // compacted gatedw, single fp16
__device__ float g_outc[(size_t)E_ * T_ * H_];   // per-expert contributions

// ---- helpers ----
__device__ __forceinline__ void split2h(float v, __half& h, __half& l) {
    h = __float2half_rn(v);
    l = __float2half_rn(v - __half2float(h));
}

#define CP16(dst_u32, src_ptr) \
    asm volatile("cp.async.cg.shared.global [%0], [%1], 16;" :: "r"(dst_u32), "l"(src_ptr))
#define CP_COMMIT asm volatile("cp.async.commit_group;")
#define CP_WAIT1  asm volatile("cp.async.wait_group 1;")
#define CP_WAIT2  asm volatile("cp.async.wait_group 2;")

__device__ __forceinline__ void ldsm4(uint32_t& r0, uint32_t& r1, uint32_t& r2,
                                      uint32_t& r3, uint32_t addr) {
    asm volatile("ldmatrix.sync.aligned.m8n8.x4.shared.b16 {%0,%1,%2,%3}, [%4];"
        : "=r"(r0), "=r"(r1), "=r"(r2), "=r"(r3) : "r"(addr));
}

__device__ __forceinline__ void mma16816(float* acc, uint32_t a0, uint32_t a1,
                                         uint32_t a2, uint32_t a3,
                                         uint32_t b0, uint32_t b1) {
    asm volatile(
        "mma.sync.aligned.m16n8k16.row.col.f32.f16.f16.f32 "
        "{%0,%1,%2,%3}, {%4,%5,%6,%7}, {%8,%9}, {%0,%1,%2,%3};"
        : "+f"(acc[0]), "+f"(acc[1]), "+f"(acc[2]), "+f"(acc[3])
        : "r"(a0), "r"(a1), "r"(a2), "r"(a3), "r"(b0), "r"(b1));
}

// GEMM1 stage: Ahi 0, Alo 12288, B 24576; stride 36864; rows 32 fp16 + 32B pad = 96B
#define STG1_ 36864
#define NSTG1_ 3
#define SMEM1_ (NSTG1_ * STG1_)
// GEMM2 stage: A 0, B 12288; stride 24576; 4 stages
#define STG2_ 24576
#define NSTG2_ 4
#define SMEM2_ (NSTG2_ * STG2_)

// 2-term (A hi+lo) chunk, warp tile 64x64
__device__ __forceinline__ void compute_chunk2(uint32_t st, float acc[4][8][4],
                                               int a_base, int b_base) {
    uint32_t Ahi = st, Alo = st + 12288, Bs = st + 24576;
#pragma unroll
    for (int ks = 0; ks < 2; ks++) {
        int kb = ks * 32;
        uint32_t B[8][2];
#pragma unroll
        for (int p = 0; p < 4; p++) {
            uint32_t r0, r1, r2, r3;
            ldsm4(r0, r1, r2, r3, Bs + b_base + p * 1536 + kb);
            B[2 * p][0] = r0; B[2 * p][1] = r1;
            B[2 * p + 1][0] = r2; B[2 * p + 1][1] = r3;
        }
        uint32_t A[4][4];
#pragma unroll
        for (int mi = 0; mi < 4; mi++)
            ldsm4(A[mi][0], A[mi][1], A[mi][2], A[mi][3],
                  Ahi + a_base + mi * 1536 + kb);
#pragma unroll
        for (int ni = 0; ni < 8; ni++)
#pragma unroll
            for (int mi = 0; mi < 4; mi++)
                mma16816(acc[mi][ni], A[mi][0], A[mi][1], A[mi][2], A[mi][3],
                         B[ni][0], B[ni][1]);
#pragma unroll
        for (int mi = 0; mi < 4; mi++)
            ldsm4(A[mi][0], A[mi][1], A[mi][2], A[mi][3],
                  Alo + a_base + mi * 1536 + kb);
#pragma unroll
        for (int ni = 0; ni < 8; ni++)
#pragma unroll
            for (int mi = 0; mi < 4; mi++)
                mma16816(acc[mi][ni], A[mi][0], A[mi][1], A[mi][2], A[mi][3],
                         B[ni][0], B[ni][1]);
    }
}

// 1-term chunk (single-fp16 A), warp tile 64x64
__device__ __forceinline__ void compute_chunk1(uint32_t st, float acc[4][8][4],
                                               int a_base, int b_base) {
    uint32_t Ah = st, Bs = st + 12288;
#pragma unroll
    for (int ks = 0; ks < 2; ks++) {
        int kb = ks * 32;
        uint32_t B[8][2];
#pragma unroll
        for (int p = 0; p < 4; p++) {
            uint32_t r0, r1, r2, r3;
            ldsm4(r0, r1, r2, r3, Bs + b_base + p * 1536 + kb);
            B[2 * p][0] = r0; B[2 * p][1] = r1;
            B[2 * p + 1][0] = r2; B[2 * p + 1][1] = r3;
        }
        uint32_t A[4][4];
#pragma unroll
        for (int mi = 0; mi < 4; mi++)
            ldsm4(A[mi][0], A[mi][1], A[mi][2], A[mi][3],
                  Ah + a_base + mi * 1536 + kb);
#pragma unroll
        for (int ni = 0; ni < 8; ni++)
#pragma unroll
            for (int mi = 0; mi < 4; mi++)
                mma16816(acc[mi][ni], A[mi][0], A[mi][1], A[mi][2], A[mi][3],
                         B[ni][0], B[ni][1]);
    }
}

// ===========================================================================
// K_conv (merged): zero counters + split X (hi/lo fp16) + convert/transpose
// both weights to fp16.  Runs before k_route (stream order).
// blocks: [0,4096) split_x, [4096, 36864) w1 transpose, [36864, 53248) w2.
// ===========================================================================
__global__ void __launch_bounds__(256)
k_conv(const float* __restrict__ X, const float* __restrict__ gup,
       const float* __restrict__ dn) {
    __shared__ __half hs[32][36];
    int b = blockIdx.x;
    int tid = threadIdx.x;
    if (b == 0 && tid < E_) g_cnt[tid] = 0;

    if (b < 4096) {                       // ---- split X ----
        int i = b * 256 + tid;            // one float4 of X
        float4 v = ((const float4*)X)[i];
        __half h0, l0, h1, l1, h2, l2, h3, l3;
        split2h(v.x, h0, l0); split2h(v.y, h1, l1);
        split2h(v.z, h2, l2); split2h(v.w, h3, l3);
        __half2* ph = (__half2*)g_xhi;
        __half2* pl = (__half2*)g_xlo;
        ph[i * 2]     = __halves2half2(h0, h1);
        ph[i * 2 + 1] = __halves2half2(h2, h3);
        pl[i * 2]     = __halves2half2(l0, l1);
        pl[i * 2 + 1] = __halves2half2(l2, l3);
        return;
    }
    const float* src;
    __half* dst;
    int RR, CC, c0, r0, e;
    if (b < 4096 + 32768) {               // ---- gup [E][H][D] -> w1h [E][D][H] ----
        int i = b - 4096;
        RR = H_; CC = D_;
        c0 = (i & 63) * 32; r0 = ((i >> 6) & 63) * 32; e = i >> 12;
        src = gup; dst = g_w1h;
    } else {                              // ---- dn [E][F][H] -> w2h [E][H][F] ----
        int i = b - 4096 - 32768;
        RR = F_; CC = H_;
        c0 = (i & 63) * 32; r0 = ((i >> 6) & 31) * 32; e = i >> 11;
        src = dn; dst = g_w2h;
    }
    int tx = tid & 31, ty = tid >> 5;
    const float* s = src + (size_t)e * RR * CC;
#pragma unroll
    for (int j = 0; j < 4; j++)
        hs[ty + 8 * j][tx] = __float2half_rn(s[(size_t)(r0 + ty + 8 * j) * CC + c0 + tx]);
    __syncthreads();
    size_t dbase = (size_t)e * RR * CC;
#pragma unroll
    for (int j = 0; j < 4; j++) {
        int cc = c0 + ty + 8 * j;
        dst[dbase + (size_t)cc * RR + r0 + tx] = hs[tx][ty + 8 * j];
    }
}

// ===========================================================================
// K0: routing weights + per-expert compacted token lists
// ===========================================================================
__global__ void k_route(const float* __restrict__ rw, const int* __restrict__ idx) {
    int t = blockIdx.x * blockDim.x + threadIdx.x;
    if (t >= T_) return;
    float acc[E_];
    int act[E_];
#pragma unroll
    for (int j = 0; j < E_; j++) { acc[j] = 0.0f; act[j] = 0; }
    for (int k = 0; k < TOPK_; k++) {
        int e = idx[t * TOPK_ + k];
        float v = rw[t * TOPK_ + k];
#pragma unroll
        for (int j = 0; j < E_; j++)
            if (j == e) { acc[j] += v; act[j] = 1; }
    }
#pragma unroll
    for (int j = 0; j < E_; j++) {
        g_w[j * T_ + t] = acc[j];
        int s = -1;
        if (act[j]) {
            s = atomicAdd(&g_cnt[j], 1);
            g_list[j * T_ + s] = t;
        }
        g_slot[j * T_ + t] = s;
    }
}

// ===========================================================================
// K1 (gathered): g_xa[e,slot,r] = x[tok,:] @ A1[e,:,r]
// ===========================================================================
__global__ void k_loraA1(const float* __restrict__ X, const float* __restrict__ A1) {
    int warp = (blockIdx.x * blockDim.x + threadIdx.x) >> 5;
    int lane = threadIdx.x & 31;
    int e = warp / T_, slot = warp % T_;
    if (slot >= g_cnt[e]) return;
    int t = g_list[e * T_ + slot];
    const float* xrow = X + (size_t)t * H_;
    float acc[R_];
#pragma unroll
    for (int r = 0; r < R_; r++) acc[r] = 0.0f;
    for (int h0 = lane * 4; h0 < H_; h0 += 128) {
        float4 xv = *(const float4*)(xrow + h0);
        const float* a = A1 + ((size_t)e * H_ + h0) * R_;
        float xs[4] = {xv.x, xv.y, xv.z, xv.w};
#pragma unroll
        for (int qd = 0; qd < 4; qd++) {
            float4 a0 = *(const float4*)(a + qd * R_);
            float4 a1 = *(const float4*)(a + qd * R_ + 4);
            acc[0] += xs[qd] * a0.x; acc[1] += xs[qd] * a0.y;
            acc[2] += xs[qd] * a0.z; acc[3] += xs[qd] * a0.w;
            acc[4] += xs[qd] * a1.x; acc[5] += xs[qd] * a1.y;
            acc[6] += xs[qd] * a1.z; acc[7] += xs[qd] * a1.w;
        }
    }
    float keep = 0.0f;
#pragma unroll
    for (int r = 0; r < R_; r++) {
        float v = acc[r];
#pragma unroll
        for (int off = 16; off; off >>= 1) v += __shfl_xor_sync(0xffffffff, v, off);
        if (lane == r) keep = v;
    }
    if (lane < R_) g_xa[(size_t)(e * T_ + slot) * R_ + lane] = keep;
}

// ===========================================================================
// K3 (gathered): g_la2[e,slot,r] = gatedw[e,slot,:] @ A2[e,:,r]
// ===========================================================================
__global__ void k_loraA2(const float* __restrict__ A2) {
    int warp = (blockIdx.x * blockDim.x + threadIdx.x) >> 5;
    int lane = threadIdx.x & 31;
    int e = warp / T_, slot = warp % T_;
    if (slot >= g_cnt[e]) return;
    const __half* ph = g_gw + (size_t)(e * T_ + slot) * F_;
    float acc[R_];
#pragma unroll
    for (int r = 0; r < R_; r++) acc[r] = 0.0f;
    for (int f0 = lane * 4; f0 < F_; f0 += 128) {
        __half2 h0 = *(const __half2*)(ph + f0);
        __half2 h1 = *(const __half2*)(ph + f0 + 2);
        float xs[4] = {__half2float(h0.x), __half2float(h0.y),
                       __half2float(h1.x), __half2float(h1.y)};
        const float* a = A2 + ((size_t)e * F_ + f0) * R_;
#pragma unroll
        for (int qd = 0; qd < 4; qd++) {
            float4 a0 = *(const float4*)(a + qd * R_);
            float4 a1 = *(const float4*)(a + qd * R_ + 4);
            acc[0] += xs[qd] * a0.x; acc[1] += xs[qd] * a0.y;
            acc[2] += xs[qd] * a0.z; acc[3] += xs[qd] * a0.w;
            acc[4] += xs[qd] * a1.x; acc[5] += xs[qd] * a1.y;
            acc[6] += xs[qd] * a1.z; acc[7] += xs[qd] * a1.w;
        }
    }
    float keep = 0.0f;
#pragma unroll
    for (int r = 0; r < R_; r++) {
        float v = acc[r];
#pragma unroll
        for (int off = 16; off; off >>= 1) v += __shfl_xor_sync(0xffffffff, v, off);
        if (lane == r) keep = v;
    }
    if (lane < R_) g_la2[(size_t)(e * T_ + slot) * R_ + lane] = keep;
}

// ===========================================================================
// K2 (gathered): HMMA GEMM1 over active tokens of expert e
// grid (D/128, 16 max m-tiles, E), 128 threads
// ===========================================================================
__global__ void __launch_bounds__(128, 2)
k_gemm1(const float* __restrict__ bias, const float* __restrict__ B1) {
    int e = blockIdx.z, m0 = blockIdx.y * 128, n0 = blockIdx.x * 128;
    int cnt = g_cnt[e];
    if (m0 >= cnt) return;
    extern __shared__ char smem[];
    uint32_t sb = (uint32_t)__cvta_generic_to_shared(smem);
    int tid = threadIdx.x;
    int wid = tid >> 5, lane = tid & 31;
    int wr = wid >> 1, wc = wid & 1, g = lane >> 2, q = lane & 3;

    int a_base = (wr * 64 + (lane & 15)) * 96 + (lane >> 4) * 16;
    int grp = lane >> 3, wth = lane & 7;
    int b_base = (wc * 64 + wth + ((grp >= 2) ? 8 : 0)) * 96 + (grp & 1) * 16;

    int tok = g_list[e * T_ + (m0 + tid < cnt ? m0 + tid : m0)];

    float acc[4][8][4];
#pragma unroll
    for (int a = 0; a < 4; a++)
#pragma unroll
        for (int b = 0; b < 8; b++)
#pragma unroll
            for (int c = 0; c < 4; c++) acc[a][b][c] = 0.0f;

    auto issue = [&](int c, int stage) {
        int k0 = c * 32;
        uint32_t a_hi = sb + stage * STG1_ + tid * 96;
        const __half* sxh = g_xhi + (size_t)tok * H_ + k0;
        const __half* sxl = g_xlo + (size_t)tok * H_ + k0;
        const __half* swh = g_w1h + ((size_t)e * D_ + n0 + tid) * H_ + k0;
#pragma unroll
        for (int j = 0; j < 4; j++) {
            CP16(a_hi + j * 16,         sxh + j * 8);
            CP16(a_hi + 12288 + j * 16, sxl + j * 8);
            CP16(a_hi + 24576 + j * 16, swh + j * 8);
        }
    };
    issue(0, 0); CP_COMMIT;
    issue(1, 1); CP_COMMIT;
    const int NCH = H_ / 32;
    for (int c = 0; c < NCH; c++) {
        CP_WAIT1;
        __syncthreads();
        if (c + 2 < NCH) issue(c + 2, (c + 2) % NSTG1_);
        CP_COMMIT;
        compute_chunk2(sb + (c % NSTG1_) * STG1_, acc, a_base, b_base);
    }
    __syncthreads();

    // ---- epilogue ----
    float* xa_s   = (float*)smem;            // [128][8]
    float* b1_s   = (float*)(smem + 4096);   // [8][128]
    float* bias_s = (float*)(smem + 8192);   // [128]
    float* w_s    = (float*)(smem + 8704);   // [128]
    for (int i = tid; i < 1024; i += 128) {
        xa_s[i] = g_xa[((size_t)e * T_ + m0 + (i >> 3)) * 8 + (i & 7)] * SCALING_;
        b1_s[i] = B1[((size_t)e * 8 + (i >> 7)) * D_ + n0 + (i & 127)];
    }
    bias_s[tid] = bias[(size_t)e * D_ + n0 + tid];
    w_s[tid] = (m0 + tid < cnt) ? g_w[e * T_ + tok] : 0.0f;
    __syncthreads();

#pragma unroll
    for (int mi = 0; mi < 4; mi++) {
#pragma unroll
        for (int ni = 0; ni < 8; ni++) {
            int c = wc * 64 + ni * 8 + q * 2;
            float2 bia = *(const float2*)&bias_s[c];
#pragma unroll
            for (int h = 0; h < 2; h++) {
                int row = wr * 64 + mi * 16 + g + h * 8;
                if (m0 + row >= cnt) continue;
                float gate = acc[mi][ni][h * 2 + 0] + bia.x;
                float up   = acc[mi][ni][h * 2 + 1] + bia.y;
                const float* xr = &xa_s[row * 8];
#pragma unroll
                for (int p = 0; p < 8; p++) {
                    float2 b1v = *(const float2*)&b1_s[p * 128 + c];
                    gate += xr[p] * b1v.x;
                    up   += xr[p] * b1v.y;
                }
                gate = fminf(gate, LIMIT_);
                up = fminf(fmaxf(up, -LIMIT_), LIMIT_);
                float glu = gate / (1.0f + expf(-ACT_ALPHA_ * gate));
                float val = w_s[row] * (up + 1.0f) * glu;
                size_t oidx = ((size_t)e * T_ + m0 + row) * F_ + ((n0 + c) >> 1);
                g_gw[oidx] = __float2half_rn(val);
            }
        }
    }
}

// ===========================================================================
// K4 (gathered): per-expert HMMA GEMM2 (single-fp16 A) -> g_outc
// grid (H/128, 16 max m-tiles, E), 128 threads; 4-stage pipeline
// ===========================================================================
__global__ void __launch_bounds__(128, 2)
k_gemm2(const float* __restrict__ bias2, const float* __restrict__ B2) {
    int e = blockIdx.z, m0 = blockIdx.y * 128, n0 = blockIdx.x * 128;
    int cnt = g_cnt[e];
    if (m0 >= cnt) return;
    extern __shared__ char smem[];
    uint32_t sb = (uint32_t)__cvta_generic_to_shared(smem);
    int tid = threadIdx.x;
    int wid = tid >> 5, lane = tid & 31;
    int wr = wid >> 1, wc = wid & 1, g = lane >> 2, q = lane & 3;

    int a_base = (wr * 64 + (lane & 15)) * 96 + (lane >> 4) * 16;
    int grp = lane >> 3, wth = lane & 7;
    int b_base = (wc * 64 + wth + ((grp >= 2) ? 8 : 0)) * 96 + (grp & 1) * 16;

    float acc[4][8][4];
#pragma unroll
    for (int a = 0; a < 4; a++)
#pragma unroll
        for (int b = 0; b < 8; b++)
#pragma unroll
            for (int c = 0; c < 4; c++) acc[a][b][c] = 0.0f;

    auto issue = [&](int c, int stage) {
        int f0 = c * 32;
        uint32_t a_s = sb + stage * STG2_ + tid * 96;
        const __half* sah = g_gw  + ((size_t)e * T_ + m0 + tid) * F_ + f0;
        const __half* sbh = g_w2h + ((size_t)e * H_ + n0 + tid) * F_ + f0;
#pragma unroll
        for (int j = 0; j < 4; j++) {
            CP16(a_s + j * 16,         sah + j * 8);
            CP16(a_s + 12288 + j * 16, sbh + j * 8);
        }
    };
    issue(0, 0); CP_COMMIT;
    issue(1, 1); CP_COMMIT;
    issue(2, 2); CP_COMMIT;
    const int NCH = F_ / 32;
    for (int c = 0; c < NCH; c++) {
        CP_WAIT2;
        __syncthreads();
        if (c + 3 < NCH) issue(c + 3, (c + 3) & (NSTG2_ - 1));
        CP_COMMIT;
        compute_chunk1(sb + (c & (NSTG2_ - 1)) * STG2_, acc, a_base, b_base);
    }
    __syncthreads();

    // ---- epilogue: += SCALING*la2@B2 + w*bias2; store to outc ----
    float* la_s = (float*)smem;            // [128][8]
    float* b2_s = (float*)(smem + 4096);   // [8][128]
    float* bb_s = (float*)(smem + 8192);   // [128]
    float* w_s  = (float*)(smem + 8704);   // [128]
    for (int i = tid; i < 1024; i += 128) {
        la_s[i] = g_la2[((size_t)e * T_ + m0 + (i >> 3)) * 8 + (i & 7)] * SCALING_;
        b2_s[i] = B2[((size_t)e * 8 + (i >> 7)) * H_ + n0 + (i & 127)];
    }
    bb_s[tid] = bias2[(size_t)e * H_ + n0 + tid];
    {
        int gs = m0 + tid;
        w_s[tid] = (gs < cnt) ? g_w[e * T_ + g_list[e * T_ + gs]] : 0.0f;
    }
    __syncthreads();

#pragma unroll
    for (int mi = 0; mi < 4; mi++) {
#pragma unroll
        for (int ni = 0; ni < 8; ni++) {
            int c = wc * 64 + ni * 8 + q * 2;
            float2 bb = *(const float2*)&bb_s[c];
#pragma unroll
            for (int h = 0; h < 2; h++) {
                int row = wr * 64 + mi * 16 + g + h * 8;
                if (m0 + row >= cnt) continue;
                float v0 = acc[mi][ni][h * 2 + 0];
                float v1 = acc[mi][ni][h * 2 + 1];
                const float* la = &la_s[row * 8];
#pragma unroll
                for (int p = 0; p < 8; p++) {
                    float2 bv = *(const float2*)&b2_s[p * 128 + c];
                    v0 += la[p] * bv.x;
                    v1 += la[p] * bv.y;
                }
                float wt = w_s[row];
                v0 += wt * bb.x;
                v1 += wt * bb.y;
                *(float2*)(g_outc + ((size_t)e * T_ + m0 + row) * H_ + n0 + c) =
                    make_float2(v0, v1);
            }
        }
    }
}

// ===========================================================================
// K5: combine per-expert contributions -> out
// ===========================================================================
__global__ void __launch_bounds__(128)
k_combine(float* __restrict__ out) {
    int t = blockIdx.x;
    int tid = threadIdx.x;
    int slots[E_];
#pragma unroll
    for (int e = 0; e < E_; e++) slots[e] = g_slot[e * T_ + t];
#pragma unroll
    for (int k = 0; k < 4; k++) {
        int h = tid * 4 + k * 512;
        float4 acc = make_float4(0.f, 0.f, 0.f, 0.f);
#pragma unroll
        for (int e = 0; e < E_; e++) {
            int s = slots[e];
            if (s >= 0) {
                float4 v = *(const float4*)(g_outc + ((size_t)e * T_ + s) * H_ + h);
                acc.x += v.x; acc.y += v.y; acc.z += v.z; acc.w += v.w;
            }
        }
        *(float4*)(out + (size_t)t * H_ + h) = acc;
    }
}

// ===========================================================================
extern "C" void kernel_launch(void* const* d_in, const int* in_sizes, int n_in,
                              void* d_out, int out_size) {
    const float* x      = (const float*)d_in[0];
    const float* rw     = (const float*)d_in[1];
    const float* gup    = (const float*)d_in[2];
    const float* gup_b  = (const float*)d_in[3];
    const float* dn     = (const float*)d_in[4];
    const float* dn_b   = (const float*)d_in[5];
    const float* A1     = (const float*)d_in[6];
    const float* B1     = (const float*)d_in[7];
    const float* A2     = (const float*)d_in[8];
    const float* B2     = (const float*)d_in[9];
    const int*   ri     = (const int*)d_in[10];   // int32 (JAX x64 off)
    float* out = (float*)d_out;

    static bool attr_done = false;
    if (!attr_done) {
        cudaFuncSetAttribute(k_gemm1, cudaFuncAttributeMaxDynamicSharedMemorySize, SMEM1_);
        cudaFuncSetAttribute(k_gemm2, cudaFuncAttributeMaxDynamicSharedMemorySize, SMEM2_);
        attr_done = true;
    }

    k_conv<<<4096 + 32768 + 16384, 256>>>(x, gup, dn);
    k_route<<<(T_ + 127) / 128, 128>>>(rw, ri);
    k_loraA1<<<(E_ * T_) / 8, 256>>>(x, A1);
    k_gemm1<<<dim3(D_ / 128, T_ / 128, E_), 128, SMEM1_>>>(gup_b, B1);
    k_loraA2<<<(E_ * T_) / 8, 256>>>(A2);
    k_gemm2<<<dim3(H_ / 128, T_ / 128, E_), 128, SMEM2_>>>(dn_b, B2);
    k_combine<<<T_, 128>>>(out);
}

// round 9
// speedup vs baseline: 1.3089x; 1.1644x over previous
#include <cuda_runtime.h>
#include <cuda_fp16.h>
#include <cstdint>
#include <math.h>

#define E_ 8
#define H_ 2048
#define F_ 1024
#define D_ 2048
#define T_ 2048
#define TOPK_ 4
#define R_ 8
#define SCALING_ 2.0f
#define LIMIT_ 7.0f
#define ACT_ALPHA_ 1.702f

// ---- scratch (__device__ globals; allocation-free per harness rules) ----
__device__ float g_w[E_ * T_];
__device__ int   g_cnt[E_];
__device__ int   g_list[E_ * T_];
__device__ int   g_slot[E_ * T_];
__device__ float g_xa[E_ * T_ * R_];
__device__ float g_la2[E_ * T_ * R_];
__device__ __half g_xhi[(size_t)T_ * H_];
__device__ __half g_xlo[(size_t)T_ * H_];
__device__ __half g_w1h[(size_t)E_ * D_ * H_];   // gate_up^T [e][d][h]
__device__ __half g_w2h[(size_t)E_ * H_ * F_];   // down^T [e][h][f]
__device__ __half g_gw[(size_t)E_ * T_ * F_];    // compacted gatedw fp16
__device__ float g_outc[(size_t)E_ * T_ * H_];

// ---- helpers ----
__device__ __forceinline__ void split2h(float v, __half& h, __half& l) {
    h = __float2half_rn(v);
    l = __float2half_rn(v - __half2float(h));
}

#define CP16(dst_u32, src_ptr) \
    asm volatile("cp.async.cg.shared.global [%0], [%1], 16;" :: "r"(dst_u32), "l"(src_ptr))
#define CP_COMMIT asm volatile("cp.async.commit_group;")
#define CP_WAIT1  asm volatile("cp.async.wait_group 1;")
#define CP_WAIT2  asm volatile("cp.async.wait_group 2;")

__device__ __forceinline__ void ldsm4(uint32_t& r0, uint32_t& r1, uint32_t& r2,
                                      uint32_t& r3, uint32_t addr) {
    asm volatile("ldmatrix.sync.aligned.m8n8.x4.shared.b16 {%0,%1,%2,%3}, [%4];"
        : "=r"(r0), "=r"(r1), "=r"(r2), "=r"(r3) : "r"(addr));
}

__device__ __forceinline__ void mma16816(float* acc, uint32_t a0, uint32_t a1,
                                         uint32_t a2, uint32_t a3,
                                         uint32_t b0, uint32_t b1) {
    asm volatile(
        "mma.sync.aligned.m16n8k16.row.col.f32.f16.f16.f32 "
        "{%0,%1,%2,%3}, {%4,%5,%6,%7}, {%8,%9}, {%0,%1,%2,%3};"
        : "+f"(acc[0]), "+f"(acc[1]), "+f"(acc[2]), "+f"(acc[3])
        : "r"(a0), "r"(a1), "r"(a2), "r"(a3), "r"(b0), "r"(b1));
}

// GEMM1 stage: Ahi 0, Alo 12288, B 24576; stride 36864; rows 32 fp16 + 32B pad = 96B
#define STG1_ 36864
#define NSTG1_ 3
#define SMEM1_ (NSTG1_ * STG1_)
// GEMM2 stage: A 0, B 12288; stride 24576; 4 stages
#define STG2_ 24576
#define NSTG2_ 4
#define SMEM2_ (NSTG2_ * STG2_)

// 2-term (A hi+lo) chunk, warp tile 64x32 (8 warps)
__device__ __forceinline__ void compute_chunk2(uint32_t st, float acc[4][4][4],
                                               int a_base, int b_base) {
    uint32_t Ahi = st, Alo = st + 12288, Bs = st + 24576;
#pragma unroll
    for (int ks = 0; ks < 2; ks++) {
        int kb = ks * 32;
        uint32_t B[4][2];
#pragma unroll
        for (int p = 0; p < 2; p++) {
            uint32_t r0, r1, r2, r3;
            ldsm4(r0, r1, r2, r3, Bs + b_base + p * 1536 + kb);
            B[2 * p][0] = r0; B[2 * p][1] = r1;
            B[2 * p + 1][0] = r2; B[2 * p + 1][1] = r3;
        }
        uint32_t A[4][4];
#pragma unroll
        for (int mi = 0; mi < 4; mi++)
            ldsm4(A[mi][0], A[mi][1], A[mi][2], A[mi][3],
                  Ahi + a_base + mi * 1536 + kb);
#pragma unroll
        for (int ni = 0; ni < 4; ni++)
#pragma unroll
            for (int mi = 0; mi < 4; mi++)
                mma16816(acc[mi][ni], A[mi][0], A[mi][1], A[mi][2], A[mi][3],
                         B[ni][0], B[ni][1]);
#pragma unroll
        for (int mi = 0; mi < 4; mi++)
            ldsm4(A[mi][0], A[mi][1], A[mi][2], A[mi][3],
                  Alo + a_base + mi * 1536 + kb);
#pragma unroll
        for (int ni = 0; ni < 4; ni++)
#pragma unroll
            for (int mi = 0; mi < 4; mi++)
                mma16816(acc[mi][ni], A[mi][0], A[mi][1], A[mi][2], A[mi][3],
                         B[ni][0], B[ni][1]);
    }
}

// 1-term chunk (single-fp16 A), warp tile 64x32
__device__ __forceinline__ void compute_chunk1(uint32_t st, float acc[4][4][4],
                                               int a_base, int b_base) {
    uint32_t Ah = st, Bs = st + 12288;
#pragma unroll
    for (int ks = 0; ks < 2; ks++) {
        int kb = ks * 32;
        uint32_t B[4][2];
#pragma unroll
        for (int p = 0; p < 2; p++) {
            uint32_t r0, r1, r2, r3;
            ldsm4(r0, r1, r2, r3, Bs + b_base + p * 1536 + kb);
            B[2 * p][0] = r0; B[2 * p][1] = r1;
            B[2 * p + 1][0] = r2; B[2 * p + 1][1] = r3;
        }
        uint32_t A[4][4];
#pragma unroll
        for (int mi = 0; mi < 4; mi++)
            ldsm4(A[mi][0], A[mi][1], A[mi][2], A[mi][3],
                  Ah + a_base + mi * 1536 + kb);
#pragma unroll
        for (int ni = 0; ni < 4; ni++)
#pragma unroll
            for (int mi = 0; mi < 4; mi++)
                mma16816(acc[mi][ni], A[mi][0], A[mi][1], A[mi][2], A[mi][3],
                         B[ni][0], B[ni][1]);
    }
}

// ===========================================================================
// K_conv (merged): zero counters + split X + convert/transpose weights
// ===========================================================================
__global__ void __launch_bounds__(256)
k_conv(const float* __restrict__ X, const float* __restrict__ gup,
       const float* __restrict__ dn) {
    __shared__ __half hs[32][36];
    int b = blockIdx.x;
    int tid = threadIdx.x;
    if (b == 0 && tid < E_) g_cnt[tid] = 0;

    if (b < 4096) {                       // ---- split X ----
        int i = b * 256 + tid;
        float4 v = ((const float4*)X)[i];
        __half h0, l0, h1, l1, h2, l2, h3, l3;
        split2h(v.x, h0, l0); split2h(v.y, h1, l1);
        split2h(v.z, h2, l2); split2h(v.w, h3, l3);
        __half2* ph = (__half2*)g_xhi;
        __half2* pl = (__half2*)g_xlo;
        ph[i * 2]     = __halves2half2(h0, h1);
        ph[i * 2 + 1] = __halves2half2(h2, h3);
        pl[i * 2]     = __halves2half2(l0, l1);
        pl[i * 2 + 1] = __halves2half2(l2, l3);
        return;
    }
    const float* src;
    __half* dst;
    int RR, CC, c0, r0, e;
    if (b < 4096 + 32768) {               // gup [E][H][D] -> w1h [E][D][H]
        int i = b - 4096;
        RR = H_; CC = D_;
        c0 = (i & 63) * 32; r0 = ((i >> 6) & 63) * 32; e = i >> 12;
        src = gup; dst = g_w1h;
    } else {                              // dn [E][F][H] -> w2h [E][H][F]
        int i = b - 4096 - 32768;
        RR = F_; CC = H_;
        c0 = (i & 63) * 32; r0 = ((i >> 6) & 31) * 32; e = i >> 11;
        src = dn; dst = g_w2h;
    }
    int tx = tid & 31, ty = tid >> 5;
    const float* s = src + (size_t)e * RR * CC;
#pragma unroll
    for (int j = 0; j < 4; j++)
        hs[ty + 8 * j][tx] = __float2half_rn(s[(size_t)(r0 + ty + 8 * j) * CC + c0 + tx]);
    __syncthreads();
    size_t dbase = (size_t)e * RR * CC;
#pragma unroll
    for (int j = 0; j < 4; j++) {
        int cc = c0 + ty + 8 * j;
        dst[dbase + (size_t)cc * RR + r0 + tx] = hs[tx][ty + 8 * j];
    }
}

// ===========================================================================
// K0: routing weights + per-expert compacted token lists
// ===========================================================================
__global__ void k_route(const float* __restrict__ rw, const int* __restrict__ idx) {
    int t = blockIdx.x * blockDim.x + threadIdx.x;
    if (t >= T_) return;
    float acc[E_];
    int act[E_];
#pragma unroll
    for (int j = 0; j < E_; j++) { acc[j] = 0.0f; act[j] = 0; }
    for (int k = 0; k < TOPK_; k++) {
        int e = idx[t * TOPK_ + k];
        float v = rw[t * TOPK_ + k];
#pragma unroll
        for (int j = 0; j < E_; j++)
            if (j == e) { acc[j] += v; act[j] = 1; }
    }
#pragma unroll
    for (int j = 0; j < E_; j++) {
        g_w[j * T_ + t] = acc[j];
        int s = -1;
        if (act[j]) {
            s = atomicAdd(&g_cnt[j], 1);
            g_list[j * T_ + s] = t;
        }
        g_slot[j * T_ + t] = s;
    }
}

// ===========================================================================
// K1 (gathered): g_xa[e,slot,r] = x[tok,:] @ A1[e,:,r]
// ===========================================================================
__global__ void k_loraA1(const float* __restrict__ X, const float* __restrict__ A1) {
    int warp = (blockIdx.x * blockDim.x + threadIdx.x) >> 5;
    int lane = threadIdx.x & 31;
    int e = warp / T_, slot = warp % T_;
    if (slot >= g_cnt[e]) return;
    int t = g_list[e * T_ + slot];
    const float* xrow = X + (size_t)t * H_;
    float acc[R_];
#pragma unroll
    for (int r = 0; r < R_; r++) acc[r] = 0.0f;
    for (int h0 = lane * 4; h0 < H_; h0 += 128) {
        float4 xv = *(const float4*)(xrow + h0);
        const float* a = A1 + ((size_t)e * H_ + h0) * R_;
        float xs[4] = {xv.x, xv.y, xv.z, xv.w};
#pragma unroll
        for (int qd = 0; qd < 4; qd++) {
            float4 a0 = *(const float4*)(a + qd * R_);
            float4 a1 = *(const float4*)(a + qd * R_ + 4);
            acc[0] += xs[qd] * a0.x; acc[1] += xs[qd] * a0.y;
            acc[2] += xs[qd] * a0.z; acc[3] += xs[qd] * a0.w;
            acc[4] += xs[qd] * a1.x; acc[5] += xs[qd] * a1.y;
            acc[6] += xs[qd] * a1.z; acc[7] += xs[qd] * a1.w;
        }
    }
    float keep = 0.0f;
#pragma unroll
    for (int r = 0; r < R_; r++) {
        float v = acc[r];
#pragma unroll
        for (int off = 16; off; off >>= 1) v += __shfl_xor_sync(0xffffffff, v, off);
        if (lane == r) keep = v;
    }
    if (lane < R_) g_xa[(size_t)(e * T_ + slot) * R_ + lane] = keep;
}

// ===========================================================================
// K3 (gathered): g_la2[e,slot,r] = gatedw[e,slot,:] @ A2[e,:,r]
// ===========================================================================
__global__ void k_loraA2(const float* __restrict__ A2) {
    int warp = (blockIdx.x * blockDim.x + threadIdx.x) >> 5;
    int lane = threadIdx.x & 31;
    int e = warp / T_, slot = warp % T_;
    if (slot >= g_cnt[e]) return;
    const __half* ph = g_gw + (size_t)(e * T_ + slot) * F_;
    float acc[R_];
#pragma unroll
    for (int r = 0; r < R_; r++) acc[r] = 0.0f;
    for (int f0 = lane * 4; f0 < F_; f0 += 128) {
        __half2 h0 = *(const __half2*)(ph + f0);
        __half2 h1 = *(const __half2*)(ph + f0 + 2);
        float xs[4] = {__half2float(h0.x), __half2float(h0.y),
                       __half2float(h1.x), __half2float(h1.y)};
        const float* a = A2 + ((size_t)e * F_ + f0) * R_;
#pragma unroll
        for (int qd = 0; qd < 4; qd++) {
            float4 a0 = *(const float4*)(a + qd * R_);
            float4 a1 = *(const float4*)(a + qd * R_ + 4);
            acc[0] += xs[qd] * a0.x; acc[1] += xs[qd] * a0.y;
            acc[2] += xs[qd] * a0.z; acc[3] += xs[qd] * a0.w;
            acc[4] += xs[qd] * a1.x; acc[5] += xs[qd] * a1.y;
            acc[6] += xs[qd] * a1.z; acc[7] += xs[qd] * a1.w;
        }
    }
    float keep = 0.0f;
#pragma unroll
    for (int r = 0; r < R_; r++) {
        float v = acc[r];
#pragma unroll
        for (int off = 16; off; off >>= 1) v += __shfl_xor_sync(0xffffffff, v, off);
        if (lane == r) keep = v;
    }
    if (lane < R_) g_la2[(size_t)(e * T_ + slot) * R_ + lane] = keep;
}

// ===========================================================================
// K2 (gathered): HMMA GEMM1, 256 threads / 8 warps, warp tile 64x32
// grid (D/128, 16 max m-tiles, E)
// ===========================================================================
__global__ void __launch_bounds__(256, 2)
k_gemm1(const float* __restrict__ bias, const float* __restrict__ B1) {
    int e = blockIdx.z, m0 = blockIdx.y * 128, n0 = blockIdx.x * 128;
    int cnt = g_cnt[e];
    if (m0 >= cnt) return;
    extern __shared__ char smem[];
    uint32_t sb = (uint32_t)__cvta_generic_to_shared(smem);
    int tid = threadIdx.x;
    int wid = tid >> 5, lane = tid & 31;
    int wr = wid >> 2, wc = wid & 3, g = lane >> 2, q = lane & 3;

    int a_base = (wr * 64 + (lane & 15)) * 96 + (lane >> 4) * 16;
    int grp = lane >> 3, wth = lane & 7;
    int b_base = (wc * 32 + wth + ((grp >= 2) ? 8 : 0)) * 96 + (grp & 1) * 16;

    int row = tid >> 1, seg = tid & 1;
    int tok = g_list[e * T_ + (m0 + row < cnt ? m0 + row : m0)];

    float acc[4][4][4];
#pragma unroll
    for (int a = 0; a < 4; a++)
#pragma unroll
        for (int b = 0; b < 4; b++)
#pragma unroll
            for (int c = 0; c < 4; c++) acc[a][b][c] = 0.0f;

    auto issue = [&](int c, int stage) {
        int k0 = c * 32 + seg * 16;
        uint32_t d = sb + stage * STG1_ + row * 96 + seg * 32;
        const __half* sxh = g_xhi + (size_t)tok * H_ + k0;
        const __half* sxl = g_xlo + (size_t)tok * H_ + k0;
        const __half* swh = g_w1h + ((size_t)e * D_ + n0 + row) * H_ + k0;
        CP16(d,              sxh);  CP16(d + 16,          sxh + 8);
        CP16(d + 12288,      sxl);  CP16(d + 12288 + 16,  sxl + 8);
        CP16(d + 24576,      swh);  CP16(d + 24576 + 16,  swh + 8);
    };
    issue(0, 0); CP_COMMIT;
    issue(1, 1); CP_COMMIT;
    const int NCH = H_ / 32;
    for (int c = 0; c < NCH; c++) {
        CP_WAIT1;
        __syncthreads();
        if (c + 2 < NCH) issue(c + 2, (c + 2) % NSTG1_);
        CP_COMMIT;
        compute_chunk2(sb + (c % NSTG1_) * STG1_, acc, a_base, b_base);
    }
    __syncthreads();

    // ---- epilogue ----
    float* xa_s   = (float*)smem;            // [128][8]
    float* b1_s   = (float*)(smem + 4096);   // [8][128]
    float* bias_s = (float*)(smem + 8192);   // [128]
    float* w_s    = (float*)(smem + 8704);   // [128]
    for (int i = tid; i < 1024; i += 256) {
        xa_s[i] = g_xa[((size_t)e * T_ + m0 + (i >> 3)) * 8 + (i & 7)] * SCALING_;
        b1_s[i] = B1[((size_t)e * 8 + (i >> 7)) * D_ + n0 + (i & 127)];
    }
    if (tid < 128) {
        bias_s[tid] = bias[(size_t)e * D_ + n0 + tid];
        w_s[tid] = (m0 + tid < cnt) ? g_w[e * T_ + g_list[e * T_ + m0 + tid]] : 0.0f;
    }
    __syncthreads();

#pragma unroll
    for (int mi = 0; mi < 4; mi++) {
#pragma unroll
        for (int ni = 0; ni < 4; ni++) {
            int c = wc * 32 + ni * 8 + q * 2;
            float2 bia = *(const float2*)&bias_s[c];
#pragma unroll
            for (int h = 0; h < 2; h++) {
                int rr = wr * 64 + mi * 16 + g + h * 8;
                if (m0 + rr >= cnt) continue;
                float gate = acc[mi][ni][h * 2 + 0] + bia.x;
                float up   = acc[mi][ni][h * 2 + 1] + bia.y;
                const float* xr = &xa_s[rr * 8];
#pragma unroll
                for (int p = 0; p < 8; p++) {
                    float2 b1v = *(const float2*)&b1_s[p * 128 + c];
                    gate += xr[p] * b1v.x;
                    up   += xr[p] * b1v.y;
                }
                gate = fminf(gate, LIMIT_);
                up = fminf(fmaxf(up, -LIMIT_), LIMIT_);
                float glu = gate / (1.0f + expf(-ACT_ALPHA_ * gate));
                float val = w_s[rr] * (up + 1.0f) * glu;
                size_t oidx = ((size_t)e * T_ + m0 + rr) * F_ + ((n0 + c) >> 1);
                g_gw[oidx] = __float2half_rn(val);
            }
        }
    }
}

// ===========================================================================
// K4 (gathered): HMMA GEMM2 (single-fp16 A), 256 threads / 8 warps
// grid (H/128, 16 max m-tiles, E); 4-stage pipeline
// ===========================================================================
__global__ void __launch_bounds__(256, 2)
k_gemm2(const float* __restrict__ bias2, const float* __restrict__ B2) {
    int e = blockIdx.z, m0 = blockIdx.y * 128, n0 = blockIdx.x * 128;
    int cnt = g_cnt[e];
    if (m0 >= cnt) return;
    extern __shared__ char smem[];
    uint32_t sb = (uint32_t)__cvta_generic_to_shared(smem);
    int tid = threadIdx.x;
    int wid = tid >> 5, lane = tid & 31;
    int wr = wid >> 2, wc = wid & 3, g = lane >> 2, q = lane & 3;

    int a_base = (wr * 64 + (lane & 15)) * 96 + (lane >> 4) * 16;
    int grp = lane >> 3, wth = lane & 7;
    int b_base = (wc * 32 + wth + ((grp >= 2) ? 8 : 0)) * 96 + (grp & 1) * 16;

    int row = tid >> 1, seg = tid & 1;

    float acc[4][4][4];
#pragma unroll
    for (int a = 0; a < 4; a++)
#pragma unroll
        for (int b = 0; b < 4; b++)
#pragma unroll
            for (int c = 0; c < 4; c++) acc[a][b][c] = 0.0f;

    auto issue = [&](int c, int stage) {
        int f0 = c * 32 + seg * 16;
        uint32_t d = sb + stage * STG2_ + row * 96 + seg * 32;
        const __half* sah = g_gw  + ((size_t)e * T_ + m0 + row) * F_ + f0;
        const __half* sbh = g_w2h + ((size_t)e * H_ + n0 + row) * F_ + f0;
        CP16(d,             sah);  CP16(d + 16,         sah + 8);
        CP16(d + 12288,     sbh);  CP16(d + 12288 + 16, sbh + 8);
    };
    issue(0, 0); CP_COMMIT;
    issue(1, 1); CP_COMMIT;
    issue(2, 2); CP_COMMIT;
    const int NCH = F_ / 32;
    for (int c = 0; c < NCH; c++) {
        CP_WAIT2;
        __syncthreads();
        if (c + 3 < NCH) issue(c + 3, (c + 3) & (NSTG2_ - 1));
        CP_COMMIT;
        compute_chunk1(sb + (c & (NSTG2_ - 1)) * STG2_, acc, a_base, b_base);
    }
    __syncthreads();

    // ---- epilogue: += SCALING*la2@B2 + w*bias2; store to outc ----
    float* la_s = (float*)smem;            // [128][8]
    float* b2_s = (float*)(smem + 4096);   // [8][128]
    float* bb_s = (float*)(smem + 8192);   // [128]
    float* w_s  = (float*)(smem + 8704);   // [128]
    for (int i = tid; i < 1024; i += 256) {
        la_s[i] = g_la2[((size_t)e * T_ + m0 + (i >> 3)) * 8 + (i & 7)] * SCALING_;
        b2_s[i] = B2[((size_t)e * 8 + (i >> 7)) * H_ + n0 + (i & 127)];
    }
    if (tid < 128) {
        bb_s[tid] = bias2[(size_t)e * H_ + n0 + tid];
        w_s[tid] = (m0 + tid < cnt) ? g_w[e * T_ + g_list[e * T_ + m0 + tid]] : 0.0f;
    }
    __syncthreads();

#pragma unroll
    for (int mi = 0; mi < 4; mi++) {
#pragma unroll
        for (int ni = 0; ni < 4; ni++) {
            int c = wc * 32 + ni * 8 + q * 2;
            float2 bb = *(const float2*)&bb_s[c];
#pragma unroll
            for (int h = 0; h < 2; h++) {
                int rr = wr * 64 + mi * 16 + g + h * 8;
                if (m0 + rr >= cnt) continue;
                float v0 = acc[mi][ni][h * 2 + 0];
                float v1 = acc[mi][ni][h * 2 + 1];
                const float* la = &la_s[rr * 8];
#pragma unroll
                for (int p = 0; p < 8; p++) {
                    float2 bv = *(const float2*)&b2_s[p * 128 + c];
                    v0 += la[p] * bv.x;
                    v1 += la[p] * bv.y;
                }
                float wt = w_s[rr];
                v0 += wt * bb.x;
                v1 += wt * bb.y;
                *(float2*)(g_outc + ((size_t)e * T_ + m0 + rr) * H_ + n0 + c) =
                    make_float2(v0, v1);
            }
        }
    }
}

// ===========================================================================
// K5: combine per-expert contributions -> out
// ===========================================================================
__global__ void __launch_bounds__(128)
k_combine(float* __restrict__ out) {
    int t = blockIdx.x;
    int tid = threadIdx.x;
    int slots[E_];
#pragma unroll
    for (int e = 0; e < E_; e++) slots[e] = g_slot[e * T_ + t];
#pragma unroll
    for (int k = 0; k < 4; k++) {
        int h = tid * 4 + k * 512;
        float4 acc = make_float4(0.f, 0.f, 0.f, 0.f);
#pragma unroll
        for (int e = 0; e < E_; e++) {
            int s = slots[e];
            if (s >= 0) {
                float4 v = *(const float4*)(g_outc + ((size_t)e * T_ + s) * H_ + h);
                acc.x += v.x; acc.y += v.y; acc.z += v.z; acc.w += v.w;
            }
        }
        *(float4*)(out + (size_t)t * H_ + h) = acc;
    }
}

// ===========================================================================
extern "C" void kernel_launch(void* const* d_in, const int* in_sizes, int n_in,
                              void* d_out, int out_size) {
    const float* x      = (const float*)d_in[0];
    const float* rw     = (const float*)d_in[1];
    const float* gup    = (const float*)d_in[2];
    const float* gup_b  = (const float*)d_in[3];
    const float* dn     = (const float*)d_in[4];
    const float* dn_b   = (const float*)d_in[5];
    const float* A1     = (const float*)d_in[6];
    const float* B1     = (const float*)d_in[7];
    const float* A2     = (const float*)d_in[8];
    const float* B2     = (const float*)d_in[9];
    const int*   ri     = (const int*)d_in[10];   // int32 (JAX x64 off)
    float* out = (float*)d_out;

    static bool attr_done = false;
    if (!attr_done) {
        cudaFuncSetAttribute(k_gemm1, cudaFuncAttributeMaxDynamicSharedMemorySize, SMEM1_);
        cudaFuncSetAttribute(k_gemm2, cudaFuncAttributeMaxDynamicSharedMemorySize, SMEM2_);
        attr_done = true;
    }

    k_conv<<<4096 + 32768 + 16384, 256>>>(x, gup, dn);
    k_route<<<(T_ + 127) / 128, 128>>>(rw, ri);
    k_loraA1<<<(E_ * T_) / 8, 256>>>(x, A1);
    k_gemm1<<<dim3(D_ / 128, T_ / 128, E_), 256, SMEM1_>>>(gup_b, B1);
    k_loraA2<<<(E_ * T_) / 8, 256>>>(A2);
    k_gemm2<<<dim3(H_ / 128, T_ / 128, E_), 256, SMEM2_>>>(dn_b, B2);
    k_combine<<<T_, 128>>>(out);
}

// round 10
// speedup vs baseline: 1.6090x; 1.2293x over previous
#include <cuda_runtime.h>
#include <cuda_fp16.h>
#include <cstdint>
#include <math.h>

#define E_ 8
#define H_ 2048
#define F_ 1024
#define D_ 2048
#define T_ 2048
#define TOPK_ 4
#define R_ 8
#define SCALING_ 2.0f
#define LIMIT_ 7.0f
#define ACT_ALPHA_ 1.702f

// ---- scratch (__device__ globals; allocation-free per harness rules) ----
__device__ float g_w[E_ * T_];
__device__ int   g_cnt[E_];
__device__ int   g_list[E_ * T_];
__device__ int   g_slot[E_ * T_];
__device__ float g_xa[E_ * T_ * R_];
__device__ float g_la2[E_ * T_ * R_];
__device__ __half g_xh[(size_t)T_ * H_];         // x in fp16
__device__ __half g_w1h[(size_t)E_ * D_ * H_];   // gate_up^T [e][d][h]
__device__ __half g_w2h[(size_t)E_ * H_ * F_];   // down^T [e][h][f]
__device__ __half g_gw[(size_t)E_ * T_ * F_];    // compacted gatedw fp16
__device__ float g_outc[(size_t)E_ * T_ * H_];

#define CP16(dst_u32, src_ptr) \
    asm volatile("cp.async.cg.shared.global [%0], [%1], 16;" :: "r"(dst_u32), "l"(src_ptr))
#define CP_COMMIT asm volatile("cp.async.commit_group;")
#define CP_WAIT2  asm volatile("cp.async.wait_group 2;")

__device__ __forceinline__ void ldsm4(uint32_t& r0, uint32_t& r1, uint32_t& r2,
                                      uint32_t& r3, uint32_t addr) {
    asm volatile("ldmatrix.sync.aligned.m8n8.x4.shared.b16 {%0,%1,%2,%3}, [%4];"
        : "=r"(r0), "=r"(r1), "=r"(r2), "=r"(r3) : "r"(addr));
}

__device__ __forceinline__ void mma16816(float* acc, uint32_t a0, uint32_t a1,
                                         uint32_t a2, uint32_t a3,
                                         uint32_t b0, uint32_t b1) {
    asm volatile(
        "mma.sync.aligned.m16n8k16.row.col.f32.f16.f16.f32 "
        "{%0,%1,%2,%3}, {%4,%5,%6,%7}, {%8,%9}, {%0,%1,%2,%3};"
        : "+f"(acc[0]), "+f"(acc[1]), "+f"(acc[2]), "+f"(acc[3])
        : "r"(a0), "r"(a1), "r"(a2), "r"(a3), "r"(b0), "r"(b1));
}

// Stage (both GEMMs): A 0, B 12288; stride 24576; 4 stages; rows 32 fp16 + 32B pad
#define STG_ 24576
#define NSTG_ 4
#define SMEM_SZ_ (NSTG_ * STG_)

// 1-term fp16 chunk (k32), warp tile 64x32 (8 warps)
__device__ __forceinline__ void compute_chunk1(uint32_t st, float acc[4][4][4],
                                               int a_base, int b_base) {
    uint32_t Ah = st, Bs = st + 12288;
#pragma unroll
    for (int ks = 0; ks < 2; ks++) {
        int kb = ks * 32;
        uint32_t B[4][2];
#pragma unroll
        for (int p = 0; p < 2; p++) {
            uint32_t r0, r1, r2, r3;
            ldsm4(r0, r1, r2, r3, Bs + b_base + p * 1536 + kb);
            B[2 * p][0] = r0; B[2 * p][1] = r1;
            B[2 * p + 1][0] = r2; B[2 * p + 1][1] = r3;
        }
        uint32_t A[4][4];
#pragma unroll
        for (int mi = 0; mi < 4; mi++)
            ldsm4(A[mi][0], A[mi][1], A[mi][2], A[mi][3],
                  Ah + a_base + mi * 1536 + kb);
#pragma unroll
        for (int ni = 0; ni < 4; ni++)
#pragma unroll
            for (int mi = 0; mi < 4; mi++)
                mma16816(acc[mi][ni], A[mi][0], A[mi][1], A[mi][2], A[mi][3],
                         B[ni][0], B[ni][1]);
    }
}

// ===========================================================================
// K_conv (merged): zero counters + X->fp16 + convert/transpose weights
// ===========================================================================
__global__ void __launch_bounds__(256)
k_conv(const float* __restrict__ X, const float* __restrict__ gup,
       const float* __restrict__ dn) {
    __shared__ __half hs[32][36];
    int b = blockIdx.x;
    int tid = threadIdx.x;
    if (b == 0 && tid < E_) g_cnt[tid] = 0;

    if (b < 4096) {                       // ---- convert X ----
        int i = b * 256 + tid;            // one float4
        float4 v = ((const float4*)X)[i];
        __half2* ph = (__half2*)g_xh;
        ph[i * 2]     = __halves2half2(__float2half_rn(v.x), __float2half_rn(v.y));
        ph[i * 2 + 1] = __halves2half2(__float2half_rn(v.z), __float2half_rn(v.w));
        return;
    }
    const float* src;
    __half* dst;
    int RR, CC, c0, r0, e;
    if (b < 4096 + 32768) {               // gup [E][H][D] -> w1h [E][D][H]
        int i = b - 4096;
        RR = H_; CC = D_;
        c0 = (i & 63) * 32; r0 = ((i >> 6) & 63) * 32; e = i >> 12;
        src = gup; dst = g_w1h;
    } else {                              // dn [E][F][H] -> w2h [E][H][F]
        int i = b - 4096 - 32768;
        RR = F_; CC = H_;
        c0 = (i & 63) * 32; r0 = ((i >> 6) & 31) * 32; e = i >> 11;
        src = dn; dst = g_w2h;
    }
    int tx = tid & 31, ty = tid >> 5;
    const float* s = src + (size_t)e * RR * CC;
#pragma unroll
    for (int j = 0; j < 4; j++)
        hs[ty + 8 * j][tx] = __float2half_rn(s[(size_t)(r0 + ty + 8 * j) * CC + c0 + tx]);
    __syncthreads();
    size_t dbase = (size_t)e * RR * CC;
#pragma unroll
    for (int j = 0; j < 4; j++) {
        int cc = c0 + ty + 8 * j;
        dst[dbase + (size_t)cc * RR + r0 + tx] = hs[tx][ty + 8 * j];
    }
}

// ===========================================================================
// K0: routing weights + per-expert compacted token lists
// ===========================================================================
__global__ void k_route(const float* __restrict__ rw, const int* __restrict__ idx) {
    int t = blockIdx.x * blockDim.x + threadIdx.x;
    if (t >= T_) return;
    float acc[E_];
    int act[E_];
#pragma unroll
    for (int j = 0; j < E_; j++) { acc[j] = 0.0f; act[j] = 0; }
    for (int k = 0; k < TOPK_; k++) {
        int e = idx[t * TOPK_ + k];
        float v = rw[t * TOPK_ + k];
#pragma unroll
        for (int j = 0; j < E_; j++)
            if (j == e) { acc[j] += v; act[j] = 1; }
    }
#pragma unroll
    for (int j = 0; j < E_; j++) {
        g_w[j * T_ + t] = acc[j];
        int s = -1;
        if (act[j]) {
            s = atomicAdd(&g_cnt[j], 1);
            g_list[j * T_ + s] = t;
        }
        g_slot[j * T_ + t] = s;
    }
}

// ===========================================================================
// K1 (gathered): g_xa[e,slot,r] = x[tok,:] @ A1[e,:,r]
// ===========================================================================
__global__ void k_loraA1(const float* __restrict__ X, const float* __restrict__ A1) {
    int warp = (blockIdx.x * blockDim.x + threadIdx.x) >> 5;
    int lane = threadIdx.x & 31;
    int e = warp / T_, slot = warp % T_;
    if (slot >= g_cnt[e]) return;
    int t = g_list[e * T_ + slot];
    const float* xrow = X + (size_t)t * H_;
    float acc[R_];
#pragma unroll
    for (int r = 0; r < R_; r++) acc[r] = 0.0f;
    for (int h0 = lane * 4; h0 < H_; h0 += 128) {
        float4 xv = *(const float4*)(xrow + h0);
        const float* a = A1 + ((size_t)e * H_ + h0) * R_;
        float xs[4] = {xv.x, xv.y, xv.z, xv.w};
#pragma unroll
        for (int qd = 0; qd < 4; qd++) {
            float4 a0 = *(const float4*)(a + qd * R_);
            float4 a1 = *(const float4*)(a + qd * R_ + 4);
            acc[0] += xs[qd] * a0.x; acc[1] += xs[qd] * a0.y;
            acc[2] += xs[qd] * a0.z; acc[3] += xs[qd] * a0.w;
            acc[4] += xs[qd] * a1.x; acc[5] += xs[qd] * a1.y;
            acc[6] += xs[qd] * a1.z; acc[7] += xs[qd] * a1.w;
        }
    }
    float keep = 0.0f;
#pragma unroll
    for (int r = 0; r < R_; r++) {
        float v = acc[r];
#pragma unroll
        for (int off = 16; off; off >>= 1) v += __shfl_xor_sync(0xffffffff, v, off);
        if (lane == r) keep = v;
    }
    if (lane < R_) g_xa[(size_t)(e * T_ + slot) * R_ + lane] = keep;
}

// ===========================================================================
// K3 (gathered): g_la2[e,slot,r] = gatedw[e,slot,:] @ A2[e,:,r]
// ===========================================================================
__global__ void k_loraA2(const float* __restrict__ A2) {
    int warp = (blockIdx.x * blockDim.x + threadIdx.x) >> 5;
    int lane = threadIdx.x & 31;
    int e = warp / T_, slot = warp % T_;
    if (slot >= g_cnt[e]) return;
    const __half* ph = g_gw + (size_t)(e * T_ + slot) * F_;
    float acc[R_];
#pragma unroll
    for (int r = 0; r < R_; r++) acc[r] = 0.0f;
    for (int f0 = lane * 4; f0 < F_; f0 += 128) {
        __half2 h0 = *(const __half2*)(ph + f0);
        __half2 h1 = *(const __half2*)(ph + f0 + 2);
        float xs[4] = {__half2float(h0.x), __half2float(h0.y),
                       __half2float(h1.x), __half2float(h1.y)};
        const float* a = A2 + ((size_t)e * F_ + f0) * R_;
#pragma unroll
        for (int qd = 0; qd < 4; qd++) {
            float4 a0 = *(const float4*)(a + qd * R_);
            float4 a1 = *(const float4*)(a + qd * R_ + 4);
            acc[0] += xs[qd] * a0.x; acc[1] += xs[qd] * a0.y;
            acc[2] += xs[qd] * a0.z; acc[3] += xs[qd] * a0.w;
            acc[4] += xs[qd] * a1.x; acc[5] += xs[qd] * a1.y;
            acc[6] += xs[qd] * a1.z; acc[7] += xs[qd] * a1.w;
        }
    }
    float keep = 0.0f;
#pragma unroll
    for (int r = 0; r < R_; r++) {
        float v = acc[r];
#pragma unroll
        for (int off = 16; off; off >>= 1) v += __shfl_xor_sync(0xffffffff, v, off);
        if (lane == r) keep = v;
    }
    if (lane < R_) g_la2[(size_t)(e * T_ + slot) * R_ + lane] = keep;
}

// ===========================================================================
// K2 (gathered): HMMA GEMM1 (1-term fp16), 256 threads / 8 warps, 4-stage
// grid (D/128, 16 max m-tiles, E)
// ===========================================================================
__global__ void __launch_bounds__(256, 2)
k_gemm1(const float* __restrict__ bias, const float* __restrict__ B1) {
    int e = blockIdx.z, m0 = blockIdx.y * 128, n0 = blockIdx.x * 128;
    int cnt = g_cnt[e];
    if (m0 >= cnt) return;
    extern __shared__ char smem[];
    uint32_t sb = (uint32_t)__cvta_generic_to_shared(smem);
    int tid = threadIdx.x;
    int wid = tid >> 5, lane = tid & 31;
    int wr = wid >> 2, wc = wid & 3, g = lane >> 2, q = lane & 3;

    int a_base = (wr * 64 + (lane & 15)) * 96 + (lane >> 4) * 16;
    int grp = lane >> 3, wth = lane & 7;
    int b_base = (wc * 32 + wth + ((grp >= 2) ? 8 : 0)) * 96 + (grp & 1) * 16;

    int row = tid >> 1, seg = tid & 1;
    int tok = g_list[e * T_ + (m0 + row < cnt ? m0 + row : m0)];

    float acc[4][4][4];
#pragma unroll
    for (int a = 0; a < 4; a++)
#pragma unroll
        for (int b = 0; b < 4; b++)
#pragma unroll
            for (int c = 0; c < 4; c++) acc[a][b][c] = 0.0f;

    auto issue = [&](int c, int stage) {
        int k0 = c * 32 + seg * 16;
        uint32_t d = sb + stage * STG_ + row * 96 + seg * 32;
        const __half* sxh = g_xh + (size_t)tok * H_ + k0;
        const __half* swh = g_w1h + ((size_t)e * D_ + n0 + row) * H_ + k0;
        CP16(d,             sxh);  CP16(d + 16,         sxh + 8);
        CP16(d + 12288,     swh);  CP16(d + 12288 + 16, swh + 8);
    };
    issue(0, 0); CP_COMMIT;
    issue(1, 1); CP_COMMIT;
    issue(2, 2); CP_COMMIT;
    const int NCH = H_ / 32;
    for (int c = 0; c < NCH; c++) {
        CP_WAIT2;
        __syncthreads();
        if (c + 3 < NCH) issue(c + 3, (c + 3) & (NSTG_ - 1));
        CP_COMMIT;
        compute_chunk1(sb + (c & (NSTG_ - 1)) * STG_, acc, a_base, b_base);
    }
    __syncthreads();

    // ---- epilogue ----
    float* xa_s   = (float*)smem;            // [128][8]
    float* b1_s   = (float*)(smem + 4096);   // [8][128]
    float* bias_s = (float*)(smem + 8192);   // [128]
    float* w_s    = (float*)(smem + 8704);   // [128]
    for (int i = tid; i < 1024; i += 256) {
        xa_s[i] = g_xa[((size_t)e * T_ + m0 + (i >> 3)) * 8 + (i & 7)] * SCALING_;
        b1_s[i] = B1[((size_t)e * 8 + (i >> 7)) * D_ + n0 + (i & 127)];
    }
    if (tid < 128) {
        bias_s[tid] = bias[(size_t)e * D_ + n0 + tid];
        w_s[tid] = (m0 + tid < cnt) ? g_w[e * T_ + g_list[e * T_ + m0 + tid]] : 0.0f;
    }
    __syncthreads();

#pragma unroll
    for (int mi = 0; mi < 4; mi++) {
#pragma unroll
        for (int ni = 0; ni < 4; ni++) {
            int c = wc * 32 + ni * 8 + q * 2;
            float2 bia = *(const float2*)&bias_s[c];
#pragma unroll
            for (int h = 0; h < 2; h++) {
                int rr = wr * 64 + mi * 16 + g + h * 8;
                if (m0 + rr >= cnt) continue;
                float gate = acc[mi][ni][h * 2 + 0] + bia.x;
                float up   = acc[mi][ni][h * 2 + 1] + bia.y;
                const float* xr = &xa_s[rr * 8];
#pragma unroll
                for (int p = 0; p < 8; p++) {
                    float2 b1v = *(const float2*)&b1_s[p * 128 + c];
                    gate += xr[p] * b1v.x;
                    up   += xr[p] * b1v.y;
                }
                gate = fminf(gate, LIMIT_);
                up = fminf(fmaxf(up, -LIMIT_), LIMIT_);
                float glu = gate / (1.0f + expf(-ACT_ALPHA_ * gate));
                float val = w_s[rr] * (up + 1.0f) * glu;
                size_t oidx = ((size_t)e * T_ + m0 + rr) * F_ + ((n0 + c) >> 1);
                g_gw[oidx] = __float2half_rn(val);
            }
        }
    }
}

// ===========================================================================
// K4 (gathered): HMMA GEMM2 (1-term fp16), 256 threads / 8 warps, 4-stage
// grid (H/128, 16 max m-tiles, E)
// ===========================================================================
__global__ void __launch_bounds__(256, 2)
k_gemm2(const float* __restrict__ bias2, const float* __restrict__ B2) {
    int e = blockIdx.z, m0 = blockIdx.y * 128, n0 = blockIdx.x * 128;
    int cnt = g_cnt[e];
    if (m0 >= cnt) return;
    extern __shared__ char smem[];
    uint32_t sb = (uint32_t)__cvta_generic_to_shared(smem);
    int tid = threadIdx.x;
    int wid = tid >> 5, lane = tid & 31;
    int wr = wid >> 2, wc = wid & 3, g = lane >> 2, q = lane & 3;

    int a_base = (wr * 64 + (lane & 15)) * 96 + (lane >> 4) * 16;
    int grp = lane >> 3, wth = lane & 7;
    int b_base = (wc * 32 + wth + ((grp >= 2) ? 8 : 0)) * 96 + (grp & 1) * 16;

    int row = tid >> 1, seg = tid & 1;

    float acc[4][4][4];
#pragma unroll
    for (int a = 0; a < 4; a++)
#pragma unroll
        for (int b = 0; b < 4; b++)
#pragma unroll
            for (int c = 0; c < 4; c++) acc[a][b][c] = 0.0f;

    auto issue = [&](int c, int stage) {
        int f0 = c * 32 + seg * 16;
        uint32_t d = sb + stage * STG_ + row * 96 + seg * 32;
        const __half* sah = g_gw  + ((size_t)e * T_ + m0 + row) * F_ + f0;
        const __half* sbh = g_w2h + ((size_t)e * H_ + n0 + row) * F_ + f0;
        CP16(d,             sah);  CP16(d + 16,         sah + 8);
        CP16(d + 12288,     sbh);  CP16(d + 12288 + 16, sbh + 8);
    };
    issue(0, 0); CP_COMMIT;
    issue(1, 1); CP_COMMIT;
    issue(2, 2); CP_COMMIT;
    const int NCH = F_ / 32;
    for (int c = 0; c < NCH; c++) {
        CP_WAIT2;
        __syncthreads();
        if (c + 3 < NCH) issue(c + 3, (c + 3) & (NSTG_ - 1));
        CP_COMMIT;
        compute_chunk1(sb + (c & (NSTG_ - 1)) * STG_, acc, a_base, b_base);
    }
    __syncthreads();

    // ---- epilogue: += SCALING*la2@B2 + w*bias2; store to outc ----
    float* la_s = (float*)smem;            // [128][8]
    float* b2_s = (float*)(smem + 4096);   // [8][128]
    float* bb_s = (float*)(smem + 8192);   // [128]
    float* w_s  = (float*)(smem + 8704);   // [128]
    for (int i = tid; i < 1024; i += 256) {
        la_s[i] = g_la2[((size_t)e * T_ + m0 + (i >> 3)) * 8 + (i & 7)] * SCALING_;
        b2_s[i] = B2[((size_t)e * 8 + (i >> 7)) * H_ + n0 + (i & 127)];
    }
    if (tid < 128) {
        bb_s[tid] = bias2[(size_t)e * H_ + n0 + tid];
        w_s[tid] = (m0 + tid < cnt) ? g_w[e * T_ + g_list[e * T_ + m0 + tid]] : 0.0f;
    }
    __syncthreads();

#pragma unroll
    for (int mi = 0; mi < 4; mi++) {
#pragma unroll
        for (int ni = 0; ni < 4; ni++) {
            int c = wc * 32 + ni * 8 + q * 2;
            float2 bb = *(const float2*)&bb_s[c];
#pragma unroll
            for (int h = 0; h < 2; h++) {
                int rr = wr * 64 + mi * 16 + g + h * 8;
                if (m0 + rr >= cnt) continue;
                float v0 = acc[mi][ni][h * 2 + 0];
                float v1 = acc[mi][ni][h * 2 + 1];
                const float* la = &la_s[rr * 8];
#pragma unroll
                for (int p = 0; p < 8; p++) {
                    float2 bv = *(const float2*)&b2_s[p * 128 + c];
                    v0 += la[p] * bv.x;
                    v1 += la[p] * bv.y;
                }
                float wt = w_s[rr];
                v0 += wt * bb.x;
                v1 += wt * bb.y;
                *(float2*)(g_outc + ((size_t)e * T_ + m0 + rr) * H_ + n0 + c) =
                    make_float2(v0, v1);
            }
        }
    }
}

// ===========================================================================
// K5: combine per-expert contributions -> out
// ===========================================================================
__global__ void __launch_bounds__(128)
k_combine(float* __restrict__ out) {
    int t = blockIdx.x;
    int tid = threadIdx.x;
    int slots[E_];
#pragma unroll
    for (int e = 0; e < E_; e++) slots[e] = g_slot[e * T_ + t];
#pragma unroll
    for (int k = 0; k < 4; k++) {
        int h = tid * 4 + k * 512;
        float4 acc = make_float4(0.f, 0.f, 0.f, 0.f);
#pragma unroll
        for (int e = 0; e < E_; e++) {
            int s = slots[e];
            if (s >= 0) {
                float4 v = *(const float4*)(g_outc + ((size_t)e * T_ + s) * H_ + h);
                acc.x += v.x; acc.y += v.y; acc.z += v.z; acc.w += v.w;
            }
        }
        *(float4*)(out + (size_t)t * H_ + h) = acc;
    }
}

// ===========================================================================
extern "C" void kernel_launch(void* const* d_in, const int* in_sizes, int n_in,
                              void* d_out, int out_size) {
    const float* x      = (const float*)d_in[0];
    const float* rw     = (const float*)d_in[1];
    const float* gup    = (const float*)d_in[2];
    const float* gup_b  = (const float*)d_in[3];
    const float* dn     = (const float*)d_in[4];
    const float* dn_b   = (const float*)d_in[5];
    const float* A1     = (const float*)d_in[6];
    const float* B1     = (const float*)d_in[7];
    const float* A2     = (const float*)d_in[8];
    const float* B2     = (const float*)d_in[9];
    const int*   ri     = (const int*)d_in[10];   // int32 (JAX x64 off)
    float* out = (float*)d_out;

    static bool attr_done = false;
    if (!attr_done) {
        cudaFuncSetAttribute(k_gemm1, cudaFuncAttributeMaxDynamicSharedMemorySize, SMEM_SZ_);
        cudaFuncSetAttribute(k_gemm2, cudaFuncAttributeMaxDynamicSharedMemorySize, SMEM_SZ_);
        attr_done = true;
    }

    k_conv<<<4096 + 32768 + 16384, 256>>>(x, gup, dn);
    k_route<<<(T_ + 127) / 128, 128>>>(rw, ri);
    k_loraA1<<<(E_ * T_) / 8, 256>>>(x, A1);
    k_gemm1<<<dim3(D_ / 128, T_ / 128, E_), 256, SMEM_SZ_>>>(gup_b, B1);
    k_loraA2<<<(E_ * T_) / 8, 256>>>(A2);
    k_gemm2<<<dim3(H_ / 128, T_ / 128, E_), 256, SMEM_SZ_>>>(dn_b, B2);
    k_combine<<<T_, 128>>>(out);
}

// round 11
// speedup vs baseline: 1.8036x; 1.1209x over previous
#include <cuda_runtime.h>
#include <cuda_fp16.h>
#include <cstdint>
#include <math.h>

#define E_ 8
#define H_ 2048
#define F_ 1024
#define D_ 2048
#define T_ 2048
#define TOPK_ 4
#define R_ 8
#define SCALING_ 2.0f
#define LIMIT_ 7.0f
#define ACT_ALPHA_ 1.702f

// ---- scratch (__device__ globals; allocation-free per harness rules) ----
__device__ float g_w[E_ * T_];
__device__ int   g_cnt[E_];
__device__ int   g_list[E_ * T_];
__device__ int   g_slot[E_ * T_];
__device__ float g_xa[E_ * T_ * R_];
__device__ float g_la2[E_ * T_ * R_];
__device__ __half g_xh[(size_t)T_ * H_];         // x in fp16
__device__ __half g_w1h[(size_t)E_ * D_ * H_];   // gate_up^T [e][d][h]
__device__ __half g_w2h[(size_t)E_ * H_ * F_];   // down^T [e][h][f]
__device__ __half g_gw[(size_t)E_ * T_ * F_];    // compacted gatedw fp16
__device__ float g_outc[(size_t)E_ * T_ * H_];

#define CP16(dst_u32, src_ptr) \
    asm volatile("cp.async.cg.shared.global [%0], [%1], 16;" :: "r"(dst_u32), "l"(src_ptr))
#define CP_COMMIT asm volatile("cp.async.commit_group;")
#define CP_WAIT2  asm volatile("cp.async.wait_group 2;")

__device__ __forceinline__ void ldsm4(uint32_t& r0, uint32_t& r1, uint32_t& r2,
                                      uint32_t& r3, uint32_t addr) {
    asm volatile("ldmatrix.sync.aligned.m8n8.x4.shared.b16 {%0,%1,%2,%3}, [%4];"
        : "=r"(r0), "=r"(r1), "=r"(r2), "=r"(r3) : "r"(addr));
}

__device__ __forceinline__ void mma16816(float* acc, uint32_t a0, uint32_t a1,
                                         uint32_t a2, uint32_t a3,
                                         uint32_t b0, uint32_t b1) {
    asm volatile(
        "mma.sync.aligned.m16n8k16.row.col.f32.f16.f16.f32 "
        "{%0,%1,%2,%3}, {%4,%5,%6,%7}, {%8,%9}, {%0,%1,%2,%3};"
        : "+f"(acc[0]), "+f"(acc[1]), "+f"(acc[2]), "+f"(acc[3])
        : "r"(a0), "r"(a1), "r"(a2), "r"(a3), "r"(b0), "r"(b1));
}

// Stage: A 0, B 10240; rows 32 fp16 (64B) + 16B pad = 80B (conflict-free:
// (20*r) mod 32 hits all 8 bank-groups across any 8 consecutive rows).
// 128 rows * 80B = 10240 per array; stage 20480; 4 stages.
#define ROWB_ 80
#define ASZ_ 10240
#define STG_ 20480
#define NSTG_ 4
#define SMEM_SZ_ (NSTG_ * STG_)
#define MISTR_ (16 * ROWB_)   // 1280

// 1-term fp16 chunk (k32), warp tile 64x32 (8 warps)
__device__ __forceinline__ void compute_chunk1(uint32_t st, float acc[4][4][4],
                                               int a_base, int b_base) {
    uint32_t Ah = st, Bs = st + ASZ_;
#pragma unroll
    for (int ks = 0; ks < 2; ks++) {
        int kb = ks * 32;
        uint32_t B[4][2];
#pragma unroll
        for (int p = 0; p < 2; p++) {
            uint32_t r0, r1, r2, r3;
            ldsm4(r0, r1, r2, r3, Bs + b_base + p * MISTR_ + kb);
            B[2 * p][0] = r0; B[2 * p][1] = r1;
            B[2 * p + 1][0] = r2; B[2 * p + 1][1] = r3;
        }
        uint32_t A[4][4];
#pragma unroll
        for (int mi = 0; mi < 4; mi++)
            ldsm4(A[mi][0], A[mi][1], A[mi][2], A[mi][3],
                  Ah + a_base + mi * MISTR_ + kb);
#pragma unroll
        for (int ni = 0; ni < 4; ni++)
#pragma unroll
            for (int mi = 0; mi < 4; mi++)
                mma16816(acc[mi][ni], A[mi][0], A[mi][1], A[mi][2], A[mi][3],
                         B[ni][0], B[ni][1]);
    }
}

// ===========================================================================
// K_conv (merged): zero counters + X->fp16 + convert/transpose weights
// ===========================================================================
__global__ void __launch_bounds__(256)
k_conv(const float* __restrict__ X, const float* __restrict__ gup,
       const float* __restrict__ dn) {
    __shared__ __half hs[32][36];
    int b = blockIdx.x;
    int tid = threadIdx.x;
    if (b == 0 && tid < E_) g_cnt[tid] = 0;

    if (b < 4096) {                       // ---- convert X ----
        int i = b * 256 + tid;            // one float4
        float4 v = ((const float4*)X)[i];
        __half2* ph = (__half2*)g_xh;
        ph[i * 2]     = __halves2half2(__float2half_rn(v.x), __float2half_rn(v.y));
        ph[i * 2 + 1] = __halves2half2(__float2half_rn(v.z), __float2half_rn(v.w));
        return;
    }
    const float* src;
    __half* dst;
    int RR, CC, c0, r0, e;
    if (b < 4096 + 32768) {               // gup [E][H][D] -> w1h [E][D][H]
        int i = b - 4096;
        RR = H_; CC = D_;
        c0 = (i & 63) * 32; r0 = ((i >> 6) & 63) * 32; e = i >> 12;
        src = gup; dst = g_w1h;
    } else {                              // dn [E][F][H] -> w2h [E][H][F]
        int i = b - 4096 - 32768;
        RR = F_; CC = H_;
        c0 = (i & 63) * 32; r0 = ((i >> 6) & 31) * 32; e = i >> 11;
        src = dn; dst = g_w2h;
    }
    int tx = tid & 31, ty = tid >> 5;
    const float* s = src + (size_t)e * RR * CC;
#pragma unroll
    for (int j = 0; j < 4; j++)
        hs[ty + 8 * j][tx] = __float2half_rn(s[(size_t)(r0 + ty + 8 * j) * CC + c0 + tx]);
    __syncthreads();
    size_t dbase = (size_t)e * RR * CC;
#pragma unroll
    for (int j = 0; j < 4; j++) {
        int cc = c0 + ty + 8 * j;
        dst[dbase + (size_t)cc * RR + r0 + tx] = hs[tx][ty + 8 * j];
    }
}

// ===========================================================================
// K0: routing weights + per-expert compacted token lists
// ===========================================================================
__global__ void k_route(const float* __restrict__ rw, const int* __restrict__ idx) {
    int t = blockIdx.x * blockDim.x + threadIdx.x;
    if (t >= T_) return;
    float acc[E_];
    int act[E_];
#pragma unroll
    for (int j = 0; j < E_; j++) { acc[j] = 0.0f; act[j] = 0; }
    for (int k = 0; k < TOPK_; k++) {
        int e = idx[t * TOPK_ + k];
        float v = rw[t * TOPK_ + k];
#pragma unroll
        for (int j = 0; j < E_; j++)
            if (j == e) { acc[j] += v; act[j] = 1; }
    }
#pragma unroll
    for (int j = 0; j < E_; j++) {
        g_w[j * T_ + t] = acc[j];
        int s = -1;
        if (act[j]) {
            s = atomicAdd(&g_cnt[j], 1);
            g_list[j * T_ + s] = t;
        }
        g_slot[j * T_ + t] = s;
    }
}

// ===========================================================================
// K1 (gathered): g_xa[e,slot,r] = x[tok,:] @ A1[e,:,r]
// ===========================================================================
__global__ void k_loraA1(const float* __restrict__ X, const float* __restrict__ A1) {
    int warp = (blockIdx.x * blockDim.x + threadIdx.x) >> 5;
    int lane = threadIdx.x & 31;
    int e = warp / T_, slot = warp % T_;
    if (slot >= g_cnt[e]) return;
    int t = g_list[e * T_ + slot];
    const float* xrow = X + (size_t)t * H_;
    float acc[R_];
#pragma unroll
    for (int r = 0; r < R_; r++) acc[r] = 0.0f;
    for (int h0 = lane * 4; h0 < H_; h0 += 128) {
        float4 xv = *(const float4*)(xrow + h0);
        const float* a = A1 + ((size_t)e * H_ + h0) * R_;
        float xs[4] = {xv.x, xv.y, xv.z, xv.w};
#pragma unroll
        for (int qd = 0; qd < 4; qd++) {
            float4 a0 = *(const float4*)(a + qd * R_);
            float4 a1 = *(const float4*)(a + qd * R_ + 4);
            acc[0] += xs[qd] * a0.x; acc[1] += xs[qd] * a0.y;
            acc[2] += xs[qd] * a0.z; acc[3] += xs[qd] * a0.w;
            acc[4] += xs[qd] * a1.x; acc[5] += xs[qd] * a1.y;
            acc[6] += xs[qd] * a1.z; acc[7] += xs[qd] * a1.w;
        }
    }
    float keep = 0.0f;
#pragma unroll
    for (int r = 0; r < R_; r++) {
        float v = acc[r];
#pragma unroll
        for (int off = 16; off; off >>= 1) v += __shfl_xor_sync(0xffffffff, v, off);
        if (lane == r) keep = v;
    }
    if (lane < R_) g_xa[(size_t)(e * T_ + slot) * R_ + lane] = keep;
}

// ===========================================================================
// K3 (gathered): g_la2[e,slot,r] = gatedw[e,slot,:] @ A2[e,:,r]
// ===========================================================================
__global__ void k_loraA2(const float* __restrict__ A2) {
    int warp = (blockIdx.x * blockDim.x + threadIdx.x) >> 5;
    int lane = threadIdx.x & 31;
    int e = warp / T_, slot = warp % T_;
    if (slot >= g_cnt[e]) return;
    const __half* ph = g_gw + (size_t)(e * T_ + slot) * F_;
    float acc[R_];
#pragma unroll
    for (int r = 0; r < R_; r++) acc[r] = 0.0f;
    for (int f0 = lane * 4; f0 < F_; f0 += 128) {
        __half2 h0 = *(const __half2*)(ph + f0);
        __half2 h1 = *(const __half2*)(ph + f0 + 2);
        float xs[4] = {__half2float(h0.x), __half2float(h0.y),
                       __half2float(h1.x), __half2float(h1.y)};
        const float* a = A2 + ((size_t)e * F_ + f0) * R_;
#pragma unroll
        for (int qd = 0; qd < 4; qd++) {
            float4 a0 = *(const float4*)(a + qd * R_);
            float4 a1 = *(const float4*)(a + qd * R_ + 4);
            acc[0] += xs[qd] * a0.x; acc[1] += xs[qd] * a0.y;
            acc[2] += xs[qd] * a0.z; acc[3] += xs[qd] * a0.w;
            acc[4] += xs[qd] * a1.x; acc[5] += xs[qd] * a1.y;
            acc[6] += xs[qd] * a1.z; acc[7] += xs[qd] * a1.w;
        }
    }
    float keep = 0.0f;
#pragma unroll
    for (int r = 0; r < R_; r++) {
        float v = acc[r];
#pragma unroll
        for (int off = 16; off; off >>= 1) v += __shfl_xor_sync(0xffffffff, v, off);
        if (lane == r) keep = v;
    }
    if (lane < R_) g_la2[(size_t)(e * T_ + slot) * R_ + lane] = keep;
}

// ===========================================================================
// K2 (gathered): HMMA GEMM1 (1-term fp16), 256 threads / 8 warps, 4-stage
// grid (D/128, 16 max m-tiles, E)
// ===========================================================================
__global__ void __launch_bounds__(256, 2)
k_gemm1(const float* __restrict__ bias, const float* __restrict__ B1) {
    int e = blockIdx.z, m0 = blockIdx.y * 128, n0 = blockIdx.x * 128;
    int cnt = g_cnt[e];
    if (m0 >= cnt) return;
    extern __shared__ char smem[];
    uint32_t sb = (uint32_t)__cvta_generic_to_shared(smem);
    int tid = threadIdx.x;
    int wid = tid >> 5, lane = tid & 31;
    int wr = wid >> 2, wc = wid & 3, g = lane >> 2, q = lane & 3;

    int a_base = (wr * 64 + (lane & 15)) * ROWB_ + (lane >> 4) * 16;
    int grp = lane >> 3, wth = lane & 7;
    int b_base = (wc * 32 + wth + ((grp >= 2) ? 8 : 0)) * ROWB_ + (grp & 1) * 16;

    int row = tid >> 1, seg = tid & 1;
    int tok = g_list[e * T_ + (m0 + row < cnt ? m0 + row : m0)];

    float acc[4][4][4];
#pragma unroll
    for (int a = 0; a < 4; a++)
#pragma unroll
        for (int b = 0; b < 4; b++)
#pragma unroll
            for (int c = 0; c < 4; c++) acc[a][b][c] = 0.0f;

    auto issue = [&](int c, int stage) {
        int k0 = c * 32 + seg * 16;
        uint32_t d = sb + stage * STG_ + row * ROWB_ + seg * 32;
        const __half* sxh = g_xh + (size_t)tok * H_ + k0;
        const __half* swh = g_w1h + ((size_t)e * D_ + n0 + row) * H_ + k0;
        CP16(d,            sxh);  CP16(d + 16,        sxh + 8);
        CP16(d + ASZ_,     swh);  CP16(d + ASZ_ + 16, swh + 8);
    };
    issue(0, 0); CP_COMMIT;
    issue(1, 1); CP_COMMIT;
    issue(2, 2); CP_COMMIT;
    const int NCH = H_ / 32;
    for (int c = 0; c < NCH; c++) {
        CP_WAIT2;
        __syncthreads();
        if (c + 3 < NCH) issue(c + 3, (c + 3) & (NSTG_ - 1));
        CP_COMMIT;
        compute_chunk1(sb + (c & (NSTG_ - 1)) * STG_, acc, a_base, b_base);
    }
    __syncthreads();

    // ---- epilogue ----
    float* xa_s   = (float*)smem;            // [128][8]
    float* b1_s   = (float*)(smem + 4096);   // [8][128]
    float* bias_s = (float*)(smem + 8192);   // [128]
    float* w_s    = (float*)(smem + 8704);   // [128]
    for (int i = tid; i < 1024; i += 256) {
        xa_s[i] = g_xa[((size_t)e * T_ + m0 + (i >> 3)) * 8 + (i & 7)] * SCALING_;
        b1_s[i] = B1[((size_t)e * 8 + (i >> 7)) * D_ + n0 + (i & 127)];
    }
    if (tid < 128) {
        bias_s[tid] = bias[(size_t)e * D_ + n0 + tid];
        w_s[tid] = (m0 + tid < cnt) ? g_w[e * T_ + g_list[e * T_ + m0 + tid]] : 0.0f;
    }
    __syncthreads();

#pragma unroll
    for (int mi = 0; mi < 4; mi++) {
#pragma unroll
        for (int ni = 0; ni < 4; ni++) {
            int c = wc * 32 + ni * 8 + q * 2;
            float2 bia = *(const float2*)&bias_s[c];
#pragma unroll
            for (int h = 0; h < 2; h++) {
                int rr = wr * 64 + mi * 16 + g + h * 8;
                if (m0 + rr >= cnt) continue;
                float gate = acc[mi][ni][h * 2 + 0] + bia.x;
                float up   = acc[mi][ni][h * 2 + 1] + bia.y;
                const float* xr = &xa_s[rr * 8];
#pragma unroll
                for (int p = 0; p < 8; p++) {
                    float2 b1v = *(const float2*)&b1_s[p * 128 + c];
                    gate += xr[p] * b1v.x;
                    up   += xr[p] * b1v.y;
                }
                gate = fminf(gate, LIMIT_);
                up = fminf(fmaxf(up, -LIMIT_), LIMIT_);
                float glu = gate / (1.0f + expf(-ACT_ALPHA_ * gate));
                float val = w_s[rr] * (up + 1.0f) * glu;
                size_t oidx = ((size_t)e * T_ + m0 + rr) * F_ + ((n0 + c) >> 1);
                g_gw[oidx] = __float2half_rn(val);
            }
        }
    }
}

// ===========================================================================
// K4 (gathered): HMMA GEMM2 (1-term fp16), 256 threads / 8 warps, 4-stage
// grid (H/128, 16 max m-tiles, E)
// ===========================================================================
__global__ void __launch_bounds__(256, 2)
k_gemm2(const float* __restrict__ bias2, const float* __restrict__ B2) {
    int e = blockIdx.z, m0 = blockIdx.y * 128, n0 = blockIdx.x * 128;
    int cnt = g_cnt[e];
    if (m0 >= cnt) return;
    extern __shared__ char smem[];
    uint32_t sb = (uint32_t)__cvta_generic_to_shared(smem);
    int tid = threadIdx.x;
    int wid = tid >> 5, lane = tid & 31;
    int wr = wid >> 2, wc = wid & 3, g = lane >> 2, q = lane & 3;

    int a_base = (wr * 64 + (lane & 15)) * ROWB_ + (lane >> 4) * 16;
    int grp = lane >> 3, wth = lane & 7;
    int b_base = (wc * 32 + wth + ((grp >= 2) ? 8 : 0)) * ROWB_ + (grp & 1) * 16;

    int row = tid >> 1, seg = tid & 1;

    float acc[4][4][4];
#pragma unroll
    for (int a = 0; a < 4; a++)
#pragma unroll
        for (int b = 0; b < 4; b++)
#pragma unroll
            for (int c = 0; c < 4; c++) acc[a][b][c] = 0.0f;

    auto issue = [&](int c, int stage) {
        int f0 = c * 32 + seg * 16;
        uint32_t d = sb + stage * STG_ + row * ROWB_ + seg * 32;
        const __half* sah = g_gw  + ((size_t)e * T_ + m0 + row) * F_ + f0;
        const __half* sbh = g_w2h + ((size_t)e * H_ + n0 + row) * F_ + f0;
        CP16(d,            sah);  CP16(d + 16,        sah + 8);
        CP16(d + ASZ_,     sbh);  CP16(d + ASZ_ + 16, sbh + 8);
    };
    issue(0, 0); CP_COMMIT;
    issue(1, 1); CP_COMMIT;
    issue(2, 2); CP_COMMIT;
    const int NCH = F_ / 32;
    for (int c = 0; c < NCH; c++) {
        CP_WAIT2;
        __syncthreads();
        if (c + 3 < NCH) issue(c + 3, (c + 3) & (NSTG_ - 1));
        CP_COMMIT;
        compute_chunk1(sb + (c & (NSTG_ - 1)) * STG_, acc, a_base, b_base);
    }
    __syncthreads();

    // ---- epilogue: += SCALING*la2@B2 + w*bias2; store to outc ----
    float* la_s = (float*)smem;            // [128][8]
    float* b2_s = (float*)(smem + 4096);   // [8][128]
    float* bb_s = (float*)(smem + 8192);   // [128]
    float* w_s  = (float*)(smem + 8704);   // [128]
    for (int i = tid; i < 1024; i += 256) {
        la_s[i] = g_la2[((size_t)e * T_ + m0 + (i >> 3)) * 8 + (i & 7)] * SCALING_;
        b2_s[i] = B2[((size_t)e * 8 + (i >> 7)) * H_ + n0 + (i & 127)];
    }
    if (tid < 128) {
        bb_s[tid] = bias2[(size_t)e * H_ + n0 + tid];
        w_s[tid] = (m0 + tid < cnt) ? g_w[e * T_ + g_list[e * T_ + m0 + tid]] : 0.0f;
    }
    __syncthreads();

#pragma unroll
    for (int mi = 0; mi < 4; mi++) {
#pragma unroll
        for (int ni = 0; ni < 4; ni++) {
            int c = wc * 32 + ni * 8 + q * 2;
            float2 bb = *(const float2*)&bb_s[c];
#pragma unroll
            for (int h = 0; h < 2; h++) {
                int rr = wr * 64 + mi * 16 + g + h * 8;
                if (m0 + rr >= cnt) continue;
                float v0 = acc[mi][ni][h * 2 + 0];
                float v1 = acc[mi][ni][h * 2 + 1];
                const float* la = &la_s[rr * 8];
#pragma unroll
                for (int p = 0; p < 8; p++) {
                    float2 bv = *(const float2*)&b2_s[p * 128 + c];
                    v0 += la[p] * bv.x;
                    v1 += la[p] * bv.y;
                }
                float wt = w_s[rr];
                v0 += wt * bb.x;
                v1 += wt * bb.y;
                *(float2*)(g_outc + ((size_t)e * T_ + m0 + rr) * H_ + n0 + c) =
                    make_float2(v0, v1);
            }
        }
    }
}

// ===========================================================================
// K5: combine per-expert contributions -> out
// ===========================================================================
__global__ void __launch_bounds__(128)
k_combine(float* __restrict__ out) {
    int t = blockIdx.x;
    int tid = threadIdx.x;
    int slots[E_];
#pragma unroll
    for (int e = 0; e < E_; e++) slots[e] = g_slot[e * T_ + t];
#pragma unroll
    for (int k = 0; k < 4; k++) {
        int h = tid * 4 + k * 512;
        float4 acc = make_float4(0.f, 0.f, 0.f, 0.f);
#pragma unroll
        for (int e = 0; e < E_; e++) {
            int s = slots[e];
            if (s >= 0) {
                float4 v = *(const float4*)(g_outc + ((size_t)e * T_ + s) * H_ + h);
                acc.x += v.x; acc.y += v.y; acc.z += v.z; acc.w += v.w;
            }
        }
        *(float4*)(out + (size_t)t * H_ + h) = acc;
    }
}

// ===========================================================================
extern "C" void kernel_launch(void* const* d_in, const int* in_sizes, int n_in,
                              void* d_out, int out_size) {
    const float* x      = (const float*)d_in[0];
    const float* rw     = (const float*)d_in[1];
    const float* gup    = (const float*)d_in[2];
    const float* gup_b  = (const float*)d_in[3];
    const float* dn     = (const float*)d_in[4];
    const float* dn_b   = (const float*)d_in[5];
    const float* A1     = (const float*)d_in[6];
    const float* B1     = (const float*)d_in[7];
    const float* A2     = (const float*)d_in[8];
    const float* B2     = (const float*)d_in[9];
    const int*   ri     = (const int*)d_in[10];   // int32 (JAX x64 off)
    float* out = (float*)d_out;

    static bool attr_done = false;
    if (!attr_done) {
        cudaFuncSetAttribute(k_gemm1, cudaFuncAttributeMaxDynamicSharedMemorySize, SMEM_SZ_);
        cudaFuncSetAttribute(k_gemm2, cudaFuncAttributeMaxDynamicSharedMemorySize, SMEM_SZ_);
        attr_done = true;
    }

    k_conv<<<4096 + 32768 + 16384, 256>>>(x, gup, dn);
    k_route<<<(T_ + 127) / 128, 128>>>(rw, ri);
    k_loraA1<<<(E_ * T_) / 8, 256>>>(x, A1);
    k_gemm1<<<dim3(D_ / 128, T_ / 128, E_), 256, SMEM_SZ_>>>(gup_b, B1);
    k_loraA2<<<(E_ * T_) / 8, 256>>>(A2);
    k_gemm2<<<dim3(H_ / 128, T_ / 128, E_), 256, SMEM_SZ_>>>(dn_b, B2);
    k_combine<<<T_, 128>>>(out);
}